// round 14
// baseline (speedup 1.0000x reference)
#include <cuda_runtime.h>
#include <cuda_fp16.h>
#include <math.h>
#include <stdint.h>

#define L_SEQ 256
#define NB    4
#define H     12
#define HD    64
#define E     768
#define FF    3072
#define NTOK  (L_SEQ * NB)   // 1024
#define NHB   (NB * H)       // 48

// ---------------- fp32 scratch ----------------
__device__ float g_qp[NB*H*L_SEQ*HD];
__device__ float g_qb[NB*H*L_SEQ];
__device__ float g_scores[NB*H*L_SEQ*L_SEQ];
__device__ float g_attnout[2*NTOK*E];      // 2 split-K partials
__device__ float g_x1[NTOK*E];
__device__ float g_ff2[4*NTOK*E];          // 4 split-K partials

// ---------------- fp16 operands ----------------
__device__ __align__(16) __half g_qh[NB*H*L_SEQ*HD], g_ql[NB*H*L_SEQ*HD];   // (n,h,l,d)*0.125 hi/lo
__device__ __align__(16) __half g_kh[NB*H*L_SEQ*HD];                        // (n,h,l,d) single
__device__ __align__(16) __half g_vTh[NB*H*HD*L_SEQ];                       // (n,h,d,l) single
__device__ __align__(16) __half g_ph[NB*H*L_SEQ*L_SEQ], g_pl[NB*H*L_SEQ*L_SEQ]; // probs hi/lo
// pre-converted fp16 weights/activations
__device__ __align__(16) __half g_wqkv[3*E*E];   // [3E, E] rows: q,k,v
__device__ __align__(16) __half g_wout[E*E];
__device__ __align__(16) __half g_w1[FF*E];
__device__ __align__(16) __half g_w2[E*FF];
__device__ __align__(16) __half g_srch[NTOK*E];
__device__ __align__(16) __half g_x1h[NTOK*E];
__device__ __align__(16) __half g_ff1h[NTOK*FF];
__device__ __align__(16) __half g_ctxh[NTOK*E];

// =================== PTX helpers (sm_80-compatible only) ===================
__device__ __forceinline__ uint32_t smem_u32(const void* p) {
    uint32_t a;
    asm("{ .reg .u64 t; cvta.to.shared.u64 t, %1; cvt.u32.u64 %0, t; }" : "=r"(a) : "l"(p));
    return a;
}
__device__ __forceinline__ void cp16(uint32_t dst, const void* src) {
    asm volatile("cp.async.cg.shared.global [%0], [%1], 16;\n" :: "r"(dst), "l"(src));
}
__device__ __forceinline__ void ldm4(uint32_t* r, uint32_t a) {
    asm volatile("ldmatrix.sync.aligned.m8n8.x4.shared.b16 {%0,%1,%2,%3}, [%4];"
                 : "=r"(r[0]), "=r"(r[1]), "=r"(r[2]), "=r"(r[3]) : "r"(a));
}
__device__ __forceinline__ void mma16816(float* d, const uint32_t* a, uint32_t b0, uint32_t b1) {
    asm volatile(
        "mma.sync.aligned.m16n8k16.row.col.f32.f16.f16.f32 "
        "{%0,%1,%2,%3}, {%4,%5,%6,%7}, {%8,%9}, {%0,%1,%2,%3};"
        : "+f"(d[0]), "+f"(d[1]), "+f"(d[2]), "+f"(d[3])
        : "r"(a[0]), "r"(a[1]), "r"(a[2]), "r"(a[3]), "r"(b0), "r"(b1));
}
__device__ __forceinline__ void pack4(float4 x, uint2& h) {
    __half2 hh0(__float2half(x.x), __float2half(x.y));
    __half2 hh1(__float2half(x.z), __float2half(x.w));
    h.x = *(uint32_t*)&hh0; h.y = *(uint32_t*)&hh1;
}
__device__ __forceinline__ void split1(float v, __half& h, __half& l) {
    h = __float2half(v);
    l = __float2half(v - __half2float(h));
}

// =================== fp32 -> fp16 convert ===================
__global__ void cvt_h(const float4* __restrict__ in, uint2* __restrict__ out, int n4)
{
    int i = blockIdx.x * blockDim.x + threadIdx.x;
    if (i >= n4) return;
    uint2 h;
    pack4(in[i], h);
    out[i] = h;
}

// ============ fp16-operand GEMM (cp.async 3-stage, 1 sync/iter) ===========
// A[M,K], B[N,K] fp16 row-major. 128x128 tile, BK=32, 8 warps.
// MODE 0: fp32 -> C + kz*M*N (bias on kz==0 if b0)
// MODE 1: bias+GELU -> fp16 C16
// MODE 2: QKV scatter (B = [3E,E] concat; b0/b1/b2 biases)
#define SA 40
#define HTILE (128 * SA * 2)            // 10240
#define HSTG  (2 * HTILE)               // 20480
#define HSM   (3 * HSTG)                // 61440

template<int MODE>
__global__ void __launch_bounds__(256, 1) hgemm(
    const __half* __restrict__ A, const __half* __restrict__ B,
    const float* __restrict__ b0, const float* __restrict__ b1, const float* __restrict__ b2,
    float* __restrict__ C, __half* __restrict__ C16,
    int M, int N, int K, int klen)
{
    extern __shared__ char smem[];
    const uint32_t sb = smem_u32(smem);
    const int tid = threadIdx.x;
    const int lane = tid & 31, wid = tid >> 5;
    const int wm = wid & 3, wn = wid >> 2;
    const int row0 = blockIdx.y * 128, col0 = blockIdx.x * 128;
    const int kz = blockIdx.z;
    const int koff = kz * klen;

    float acc[2][8][4];
#pragma unroll
    for (int i = 0; i < 2; i++)
#pragma unroll
        for (int j = 0; j < 8; j++)
#pragma unroll
            for (int r = 0; r < 4; r++) acc[i][j][r] = 0.f;

    const int niter = klen >> 5;

    auto load = [&](int it, int s) {
        const int kk = koff + it * 32;
#pragma unroll
        for (int u = 0; u < 2; u++) {
            int e = tid + u * 256;               // 0..511
            int rr = e >> 2, cc = e & 3;
            uint32_t off = (uint32_t)((rr * SA + cc * 8) * 2);
            cp16(sb + (uint32_t)(s * HSTG) + off, A + (long)(row0 + rr) * K + kk + cc * 8);
            cp16(sb + (uint32_t)(s * HSTG) + HTILE + off, B + (long)(col0 + rr) * K + kk + cc * 8);
        }
        asm volatile("cp.async.commit_group;" ::: "memory");
    };
    auto compute = [&](int s) {
        const uint32_t base = sb + (uint32_t)(s * HSTG);
#pragma unroll
        for (int ks = 0; ks < 2; ks++) {
            const uint32_t kcol = (uint32_t)((ks * 16 + (lane >> 4) * 8) * 2);
            uint32_t ah[2][4];
            const uint32_t arow = (uint32_t)(wm * 32 + (lane & 15));
#pragma unroll
            for (int t = 0; t < 2; t++) {
                uint32_t off = ((arow + t * 16) * SA) * 2 + kcol;
                ldm4(ah[t], base + off);
            }
            uint32_t bh[4][4];
            const uint32_t brow = (uint32_t)(wn * 64 + (lane & 15));
#pragma unroll
            for (int u = 0; u < 4; u++) {
                uint32_t off = ((brow + u * 16) * SA) * 2 + kcol;
                ldm4(bh[u], base + HTILE + off);
            }
#pragma unroll
            for (int mt = 0; mt < 2; mt++)
#pragma unroll
                for (int nt = 0; nt < 8; nt++) {
                    int u = nt >> 1, p = nt & 1;
                    mma16816(acc[mt][nt], ah[mt], bh[u][p], bh[u][p + 2]);
                }
        }
    };

    load(0, 0);
    int s = 0, snext = 1;
    for (int it = 0; it < niter; it++) {
        if (it + 1 < niter) {
            load(it + 1, snext);
            asm volatile("cp.async.wait_group 1;" ::: "memory");
        } else {
            asm volatile("cp.async.wait_group 0;" ::: "memory");
        }
        __syncthreads();
        compute(s);
        s = snext;
        snext = (snext == 2) ? 0 : snext + 1;
    }

    const int rl = lane >> 2, cl = (lane & 3) * 2;
#pragma unroll
    for (int mt = 0; mt < 2; mt++) {
#pragma unroll
        for (int g = 0; g < 2; g++) {
            const int m = row0 + wm * 32 + mt * 16 + g * 8 + rl;
#pragma unroll
            for (int nt = 0; nt < 8; nt++) {
                const int n = col0 + wn * 64 + nt * 8 + cl;
                float v0 = acc[mt][nt][2 * g];
                float v1 = acc[mt][nt][2 * g + 1];
                if (MODE == 0) {
                    if (b0 && kz == 0) { v0 += b0[n]; v1 += b0[n + 1]; }
                    *(float2*)(C + (long)kz * M * N + (long)m * N + n) = make_float2(v0, v1);
                } else if (MODE == 1) {
                    v0 += b0[n]; v1 += b0[n + 1];
                    v0 = 0.5f * v0 * (1.0f + erff(v0 * 0.70710678118654752f));
                    v1 = 0.5f * v1 * (1.0f + erff(v1 * 0.70710678118654752f));
                    *(__half2*)(C16 + (long)m * N + n) =
                        __half2(__float2half(v0), __float2half(v1));
                } else { // MODE 2: QKV scatter -> fp16 operand layouts
                    const int l = m >> 2, nbb = m & 3;
#pragma unroll
                    for (int q = 0; q < 2; q++) {
                        int gcol = n + q;
                        float v = q ? v1 : v0;
                        int seg = gcol / E;
                        int cc = gcol - seg * E;
                        int hh = cc >> 6, dd = cc & 63;
                        if (seg == 0) {
                            __half hb, lb;
                            split1((v + b0[cc]) * 0.125f, hb, lb);
                            long idx = (((long)(nbb * H + hh)) * L_SEQ + l) * HD + dd;
                            g_qh[idx] = hb; g_ql[idx] = lb;
                        } else if (seg == 1) {
                            long idx = (((long)(nbb * H + hh)) * L_SEQ + l) * HD + dd;
                            g_kh[idx] = __float2half(v + b1[cc]);
                        } else {
                            long idx = (((long)(nbb * H + hh)) * HD + dd) * L_SEQ + l;
                            g_vTh[idx] = __float2half(v + b2[cc]);
                        }
                    }
                }
            }
        }
    }
}

// ======= pre-split fp16 batched GEMM (attention): A hi/lo × B single ======
// 3-stage cp.async rotation, 1 sync/iter.
// MODE 0: scores fp32 -> C ; MODE 1: ctx -> fp16 C16 (scattered (l,n,e))
template<int TM, int TN, int NWM, int MODE>
__global__ void __launch_bounds__(256, 1) pgemm(
    const __half* __restrict__ Ah, const __half* __restrict__ Al,
    const __half* __restrict__ Bh,
    float* __restrict__ C, __half* __restrict__ C16, int K, long sA, long sB)
{
    constexpr int TILE_A = TM * SA * 2;
    constexpr int TILE_B = TN * SA * 2;
    constexpr int STG = 2 * TILE_A + TILE_B;
    constexpr int O_AH = 0, O_AL = TILE_A, O_BH = 2 * TILE_A;

    extern __shared__ char smem[];
    const uint32_t sb = smem_u32(smem);
    const int tid = threadIdx.x;
    const int lane = tid & 31, wid = tid >> 5;
    const int wm = wid % NWM, wn = wid / NWM;
    const int row0 = blockIdx.y * TM, col0 = blockIdx.x * TN;
    const int bz = blockIdx.z;

    const __half* pAh = Ah + (long)bz * sA;
    const __half* pAl = Al + (long)bz * sA;
    const __half* pBh = Bh + (long)bz * sB;

    float acc[2][8][4];
#pragma unroll
    for (int i = 0; i < 2; i++)
#pragma unroll
        for (int j = 0; j < 8; j++)
#pragma unroll
            for (int r = 0; r < 4; r++) acc[i][j][r] = 0.f;

    const int niter = K >> 5;

    auto load = [&](int it, int s) {
        const int koff = it * 32;
        for (int e = tid; e < TM * 4; e += 256) {
            int rr = e >> 2, cc = e & 3;
            uint32_t off = (uint32_t)((rr * SA + cc * 8) * 2);
            long go = (long)(row0 + rr) * K + koff + cc * 8;
            cp16(sb + (uint32_t)(s * STG) + O_AH + off, pAh + go);
            cp16(sb + (uint32_t)(s * STG) + O_AL + off, pAl + go);
        }
        for (int e = tid; e < TN * 4; e += 256) {
            int rr = e >> 2, cc = e & 3;
            uint32_t off = (uint32_t)((rr * SA + cc * 8) * 2);
            long go = (long)(col0 + rr) * K + koff + cc * 8;
            cp16(sb + (uint32_t)(s * STG) + O_BH + off, pBh + go);
        }
        asm volatile("cp.async.commit_group;" ::: "memory");
    };
    auto compute = [&](int s) {
        const uint32_t base = sb + (uint32_t)(s * STG);
#pragma unroll
        for (int ks = 0; ks < 2; ks++) {
            const uint32_t kcol = (uint32_t)((ks * 16 + (lane >> 4) * 8) * 2);
            uint32_t ah[2][4], al[2][4];
            const uint32_t arow = (uint32_t)(wm * 32 + (lane & 15));
#pragma unroll
            for (int t = 0; t < 2; t++) {
                uint32_t off = ((arow + t * 16) * SA) * 2 + kcol;
                ldm4(ah[t], base + O_AH + off);
                ldm4(al[t], base + O_AL + off);
            }
            uint32_t bh[4][4];
            const uint32_t brow = (uint32_t)(wn * 64 + (lane & 15));
#pragma unroll
            for (int u = 0; u < 4; u++) {
                uint32_t off = ((brow + u * 16) * SA) * 2 + kcol;
                ldm4(bh[u], base + O_BH + off);
            }
#pragma unroll
            for (int mt = 0; mt < 2; mt++)
#pragma unroll
                for (int nt = 0; nt < 8; nt++) {
                    int u = nt >> 1, p = nt & 1;
                    mma16816(acc[mt][nt], ah[mt], bh[u][p], bh[u][p + 2]);
                    mma16816(acc[mt][nt], al[mt], bh[u][p], bh[u][p + 2]);
                }
        }
    };

    load(0, 0);
    int s = 0, snext = 1;
    for (int it = 0; it < niter; it++) {
        if (it + 1 < niter) {
            load(it + 1, snext);
            asm volatile("cp.async.wait_group 1;" ::: "memory");
        } else {
            asm volatile("cp.async.wait_group 0;" ::: "memory");
        }
        __syncthreads();
        compute(s);
        s = snext;
        snext = (snext == 2) ? 0 : snext + 1;
    }

    const int rl = lane >> 2, cl = (lane & 3) * 2;
#pragma unroll
    for (int mt = 0; mt < 2; mt++) {
#pragma unroll
        for (int g = 0; g < 2; g++) {
            const int m = row0 + wm * 32 + mt * 16 + g * 8 + rl;
#pragma unroll
            for (int nt = 0; nt < 8; nt++) {
                const int n = col0 + wn * 64 + nt * 8 + cl;
                float v0 = acc[mt][nt][2 * g];
                float v1 = acc[mt][nt][2 * g + 1];
                if (MODE == 0) {
                    *(float2*)(C + (long)bz * L_SEQ * L_SEQ + (long)m * L_SEQ + n) =
                        make_float2(v0, v1);
                } else {
                    const int nb = bz / H, hh = bz % H;
                    *(__half2*)(C16 + ((long)m * NB + nb) * E + hh * HD + n) =
                        __half2(__float2half(v0), __float2half(v1));
                }
            }
        }
    }
}

// ---- qp[n,h,i,c] = sum_d q[n,h,i,d]*p_w[h*64+d,c]; qb = q . p_b ---------
__global__ void qp2_kernel(const float* __restrict__ p_w, const float* __restrict__ p_b)
{
    const int h = blockIdx.y;
    const int m0 = blockIdx.x * 64;
    __shared__ float w[64][65];
    __shared__ float qs[64][65];
    __shared__ float pb[64];
    const int tid = threadIdx.x;          // 256
    for (int e = tid; e < 4096; e += 256) {
        int d = e >> 6, c = e & 63;
        w[d][c] = p_w[(h * 64 + d) * 64 + c];
    }
    if (tid < 64) pb[tid] = p_b[h * 64 + tid];
    for (int e = tid; e < 4096; e += 256) {
        int r = e >> 6, d = e & 63;
        int mg = m0 + r;
        int n = mg >> 8, l = mg & 255;
        long idx = (((long)(n * H + h)) * L_SEQ + l) * HD + d;
        qs[r][d] = __half2float(g_qh[idx]) + __half2float(g_ql[idx]);
    }
    __syncthreads();

    const int rr = tid >> 2, cg = tid & 3;
    float acc[16];
#pragma unroll
    for (int c = 0; c < 16; c++) acc[c] = 0.f;
#pragma unroll
    for (int d = 0; d < 64; d++) {
        float qv = qs[rr][d];
#pragma unroll
        for (int c = 0; c < 16; c++) acc[c] += qv * w[d][cg * 16 + c];
    }
    const int mg = m0 + rr;
    const int n = mg >> 8, l = mg & 255;
    const long base = (((long)(n * H + h)) * L_SEQ + l) * HD;
#pragma unroll
    for (int c = 0; c < 16; c++) g_qp[base + cg * 16 + c] = acc[c];
    if (cg == 0) {
        float sb = 0.f;
#pragma unroll
        for (int d = 0; d < 64; d++) sb += qs[rr][d] * pb[d];
        g_qb[((long)n * H + h) * L_SEQ + l] = sb;
    }
}

// ---- cpm_fused: per (n,i): full score row (qk + qp@pos^T + qb), softmax,
//      write probs hi/lo.
#define CSA 72   // fp16 elements per row (64 + 8 pad)
__global__ void __launch_bounds__(256) cpm_kernel(const float* __restrict__ pos)
{
    __shared__ __align__(16) __half sAh[16 * CSA];
    __shared__ __align__(16) __half sAl[16 * CSA];
    __shared__ __align__(16) __half sB[L_SEQ * CSA];
    __shared__ float qbs[12];
    __shared__ float wred[8][12];
    __shared__ float rowv[12];

    const int b = blockIdx.x;            // n*L + i
    const int n = b >> 8, i = b & 255;
    const int tid = threadIdx.x;
    const int lane = tid & 31, wid = tid >> 5;

    for (int e = tid; e < 1024; e += 256) {
        int h = e >> 6, c = e & 63;
        float v = (h < 12) ? g_qp[(((long)(n * H + h)) * L_SEQ + i) * HD + c] : 0.f;
        __half hb, lb;
        split1(v, hb, lb);
        sAh[h * CSA + c] = hb;
        sAl[h * CSA + c] = lb;
    }
    if (tid < 12) qbs[tid] = g_qb[((long)n * H + tid) * L_SEQ + i];

    const float4* pr = (const float4*)(pos + (((long)n * L_SEQ + i) * L_SEQ) * 64);
#pragma unroll 8
    for (int u = 0; u < 16; u++) {
        int e = tid + u * 256;
        int rr = e >> 4, cc = e & 15;
        float4 v = pr[e];
        uint2 h;
        pack4(v, h);
        *(uint2*)&sB[rr * CSA + cc * 4] = h;
    }
    __syncthreads();

    const uint32_t aB = smem_u32(sAh), aL = smem_u32(sAl), bB = smem_u32(sB);
    const int n0 = wid * 32;

    float acc[4][4];
#pragma unroll
    for (int j = 0; j < 4; j++)
#pragma unroll
        for (int r = 0; r < 4; r++) acc[j][r] = 0.f;

#pragma unroll
    for (int ks = 0; ks < 4; ks++) {
        const uint32_t kcol = (uint32_t)((ks * 16 + (lane >> 4) * 8) * 2);
        uint32_t ah[4], al[4];
        {
            uint32_t off = ((uint32_t)(lane & 15) * CSA) * 2 + kcol;
            ldm4(ah, aB + off);
            ldm4(al, aL + off);
        }
        uint32_t bh[2][4];
#pragma unroll
        for (int t = 0; t < 2; t++) {
            uint32_t off = ((uint32_t)(n0 + (lane & 15) + t * 16) * CSA) * 2 + kcol;
            ldm4(bh[t], bB + off);
        }
#pragma unroll
        for (int nt = 0; nt < 4; nt++) {
            int u = nt >> 1, p = nt & 1;
            mma16816(acc[nt], ah, bh[u][p], bh[u][p + 2]);
            mma16816(acc[nt], al, bh[u][p], bh[u][p + 2]);
        }
    }

    const int rl = lane >> 2, cl = (lane & 3) * 2;
    float sc[2][8];
#pragma unroll
    for (int g = 0; g < 2; g++) {
        const int m = g * 8 + rl;
        if (m < 12) {
            const float qb = qbs[m];
            const float* srow = g_scores + ((((long)n * H + m) * L_SEQ + i) * L_SEQ);
#pragma unroll
            for (int nt = 0; nt < 4; nt++) {
                const int j = n0 + nt * 8 + cl;
                float2 qk = *(const float2*)(srow + j);
                sc[g][2 * nt]     = qk.x + acc[nt][2 * g]     + qb;
                sc[g][2 * nt + 1] = qk.y + acc[nt][2 * g + 1] + qb;
            }
        } else {
#pragma unroll
            for (int c = 0; c < 8; c++) sc[g][c] = -1e30f;
        }
    }

    float mymax[2];
#pragma unroll
    for (int g = 0; g < 2; g++) {
        float m = sc[g][0];
#pragma unroll
        for (int c = 1; c < 8; c++) m = fmaxf(m, sc[g][c]);
        m = fmaxf(m, __shfl_xor_sync(0xffffffffu, m, 1));
        m = fmaxf(m, __shfl_xor_sync(0xffffffffu, m, 2));
        mymax[g] = m;
    }
    if ((lane & 3) == 0) {
        wred[wid][rl] = mymax[0];
        if (8 + rl < 12) wred[wid][8 + rl] = mymax[1];
    }
    __syncthreads();
    if (tid < 12) {
        float m = wred[0][tid];
#pragma unroll
        for (int w = 1; w < 8; w++) m = fmaxf(m, wred[w][tid]);
        rowv[tid] = m;
    }
    __syncthreads();
    float rmax[2];
    rmax[0] = rowv[rl];
    rmax[1] = (8 + rl < 12) ? rowv[8 + rl] : 0.f;
    __syncthreads();

    float mysum[2];
#pragma unroll
    for (int g = 0; g < 2; g++) {
        float s = 0.f;
#pragma unroll
        for (int c = 0; c < 8; c++) {
            float e = __expf(sc[g][c] - rmax[g]);
            sc[g][c] = e;
            s += e;
        }
        s += __shfl_xor_sync(0xffffffffu, s, 1);
        s += __shfl_xor_sync(0xffffffffu, s, 2);
        mysum[g] = s;
    }
    if ((lane & 3) == 0) {
        wred[wid][rl] = mysum[0];
        if (8 + rl < 12) wred[wid][8 + rl] = mysum[1];
    }
    __syncthreads();
    if (tid < 12) {
        float s = 0.f;
#pragma unroll
        for (int w = 0; w < 8; w++) s += wred[w][tid];
        rowv[tid] = 1.f / s;
    }
    __syncthreads();
    float rinv[2];
    rinv[0] = rowv[rl];
    rinv[1] = (8 + rl < 12) ? rowv[8 + rl] : 0.f;

#pragma unroll
    for (int g = 0; g < 2; g++) {
        const int m = g * 8 + rl;
        if (m < 12) {
            const long rbase = (((long)n * H + m) * L_SEQ + i) * L_SEQ;
#pragma unroll
            for (int nt = 0; nt < 4; nt++) {
                const int j = n0 + nt * 8 + cl;
                float p0 = sc[g][2 * nt] * rinv[g];
                float p1 = sc[g][2 * nt + 1] * rinv[g];
                __half h0, l0, h1, l1;
                split1(p0, h0, l0);
                split1(p1, h1, l1);
                *(__half2*)(g_ph + rbase + j) = __half2(h0, h1);
                *(__half2*)(g_pl + rbase + j) = __half2(l0, l1);
            }
        }
    }
}

// ---- out = LayerNorm(a + sum partials); optional fp16 copy ---------------
__global__ void ln_multi(const float* __restrict__ a, const float* __restrict__ p,
                         int nparts, long pstride,
                         const float* __restrict__ gamma, const float* __restrict__ beta,
                         float* __restrict__ out, __half* __restrict__ out16)
{
    const int row = blockIdx.x;
    const int t = threadIdx.x;
    __shared__ float rs[8], rq[8];
    float v[3];
    float s = 0.f, s2 = 0.f;
#pragma unroll
    for (int u = 0; u < 3; u++) {
        long idx = (long)row * E + t + u * 256;
        float x = a[idx];
        for (int z = 0; z < nparts; z++) x += p[z * pstride + idx];
        v[u] = x; s += x; s2 += x * x;
    }
#pragma unroll
    for (int o = 16; o > 0; o >>= 1) {
        s  += __shfl_xor_sync(0xffffffffu, s, o);
        s2 += __shfl_xor_sync(0xffffffffu, s2, o);
    }
    if ((t & 31) == 0) { rs[t >> 5] = s; rq[t >> 5] = s2; }
    __syncthreads();
    if (t < 32) {
        float a1 = (t < 8) ? rs[t] : 0.f;
        float a2 = (t < 8) ? rq[t] : 0.f;
#pragma unroll
        for (int o = 4; o > 0; o >>= 1) {
            a1 += __shfl_xor_sync(0xffffffffu, a1, o);
            a2 += __shfl_xor_sync(0xffffffffu, a2, o);
        }
        if (t == 0) { rs[0] = a1; rq[0] = a2; }
    }
    __syncthreads();
    float mean = rs[0] * (1.f / 768.f);
    float var  = rq[0] * (1.f / 768.f) - mean * mean;
    float r = rsqrtf(var + 1e-5f);
#pragma unroll
    for (int u = 0; u < 3; u++) {
        int c = t + u * 256;
        float o = (v[u] - mean) * r * gamma[c] + beta[c];
        out[(long)row * E + c] = o;
        if (out16) out16[(long)row * E + c] = __float2half(o);
    }
}

// =================== host launcher ===================
static inline void cvt_launch(const float* in, __half* out, int n)
{
    int n4 = n / 4;
    cvt_h<<<(n4 + 255) / 256, 256>>>((const float4*)in, (uint2*)out, n4);
}

extern "C" void kernel_launch(void* const* d_in, const int* in_sizes, int n_in,
                              void* d_out, int out_size)
{
    const float* src    = (const float*)d_in[0];
    const float* pos    = (const float*)d_in[1];
    const float* q_w    = (const float*)d_in[2];
    const float* q_b    = (const float*)d_in[3];
    const float* k_w    = (const float*)d_in[4];
    const float* k_b    = (const float*)d_in[5];
    const float* v_w    = (const float*)d_in[6];
    const float* v_b    = (const float*)d_in[7];
    const float* p_w    = (const float*)d_in[8];
    const float* p_b    = (const float*)d_in[9];
    const float* out_w  = (const float*)d_in[10];
    const float* out_b  = (const float*)d_in[11];
    const float* lin1_w = (const float*)d_in[12];
    const float* lin1_b = (const float*)d_in[13];
    const float* lin2_w = (const float*)d_in[14];
    const float* lin2_b = (const float*)d_in[15];
    const float* n1_g   = (const float*)d_in[16];
    const float* n1_b   = (const float*)d_in[17];
    const float* n2_g   = (const float*)d_in[18];
    const float* n2_b   = (const float*)d_in[19];
    float* out = (float*)d_out;

    auto hg0 = hgemm<0>; auto hg1 = hgemm<1>; auto hg2 = hgemm<2>;
    auto pg_scores = pgemm<128, 128, 4, 0>;
    auto pg_ctx    = pgemm<256, 64, 8, 1>;
    const int smem_scores = 3 * (2 * 128 * SA * 2 + 128 * SA * 2);          // 92160
    const int smem_ctx    = 3 * (2 * 256 * SA * 2 + 64 * SA * 2);           // 138240
    cudaFuncSetAttribute(hg0, cudaFuncAttributeMaxDynamicSharedMemorySize, HSM);
    cudaFuncSetAttribute(hg1, cudaFuncAttributeMaxDynamicSharedMemorySize, HSM);
    cudaFuncSetAttribute(hg2, cudaFuncAttributeMaxDynamicSharedMemorySize, HSM);
    cudaFuncSetAttribute(pg_scores, cudaFuncAttributeMaxDynamicSharedMemorySize, smem_scores);
    cudaFuncSetAttribute(pg_ctx, cudaFuncAttributeMaxDynamicSharedMemorySize, smem_ctx);

    float *pscores, *pattn, *px1, *pff2;
    cudaGetSymbolAddress((void**)&pscores, g_scores);
    cudaGetSymbolAddress((void**)&pattn,   g_attnout);
    cudaGetSymbolAddress((void**)&px1,     g_x1);
    cudaGetSymbolAddress((void**)&pff2,    g_ff2);

    __half *qh, *ql, *kh, *vTh, *ph, *pl;
    __half *wqkv, *wout, *w1, *w2, *srch, *x1h, *ff1h, *ctxh;
    cudaGetSymbolAddress((void**)&qh,   g_qh);  cudaGetSymbolAddress((void**)&ql, g_ql);
    cudaGetSymbolAddress((void**)&kh,   g_kh);
    cudaGetSymbolAddress((void**)&vTh,  g_vTh);
    cudaGetSymbolAddress((void**)&ph,   g_ph);  cudaGetSymbolAddress((void**)&pl, g_pl);
    cudaGetSymbolAddress((void**)&wqkv, g_wqkv);
    cudaGetSymbolAddress((void**)&wout, g_wout);
    cudaGetSymbolAddress((void**)&w1,   g_w1);
    cudaGetSymbolAddress((void**)&w2,   g_w2);
    cudaGetSymbolAddress((void**)&srch, g_srch);
    cudaGetSymbolAddress((void**)&x1h,  g_x1h);
    cudaGetSymbolAddress((void**)&ff1h, g_ff1h);
    cudaGetSymbolAddress((void**)&ctxh, g_ctxh);

    // ---- one-time fp32 -> fp16 converts ----
    cvt_launch(q_w,    wqkv,             E * E);
    cvt_launch(k_w,    wqkv + E * E,     E * E);
    cvt_launch(v_w,    wqkv + 2 * E * E, E * E);
    cvt_launch(out_w,  wout,             E * E);
    cvt_launch(lin1_w, w1,               FF * E);
    cvt_launch(lin2_w, w2,               E * FF);
    cvt_launch(src,    srch,             NTOK * E);

    // ---- fused QKV projection ----
    hg2<<<dim3(3 * E / 128, NTOK / 128, 1), 256, HSM>>>(
        srch, wqkv, q_b, k_b, v_b, nullptr, nullptr, NTOK, 3 * E, E, E);

    // ---- attention ----
    qp2_kernel<<<dim3(16, 12), 256>>>(p_w, p_b);
    pg_scores<<<dim3(2, 2, NHB), 256, smem_scores>>>(
        qh, ql, kh, pscores, nullptr, HD, (long)L_SEQ * HD, (long)L_SEQ * HD);
    cpm_kernel<<<NB * L_SEQ, 256>>>(pos);     // fused pos-scores + softmax
    pg_ctx<<<dim3(1, 1, NHB), 256, smem_ctx>>>(
        ph, pl, vTh, nullptr, ctxh, L_SEQ, (long)L_SEQ * L_SEQ, (long)HD * L_SEQ);

    // ---- output projection (split-K=2) ----
    hg0<<<dim3(E / 128, NTOK / 128, 2), 256, HSM>>>(
        ctxh, wout, out_b, nullptr, nullptr, pattn, nullptr, NTOK, E, E, E / 2);

    // ---- x1 = LN(src + partials) ----
    ln_multi<<<NTOK, 256>>>(src, pattn, 2, (long)NTOK * E, n1_g, n1_b, px1, x1h);

    // ---- FFN ----
    hg1<<<dim3(FF / 128, NTOK / 128, 1), 256, HSM>>>(
        x1h, w1, lin1_b, nullptr, nullptr, nullptr, ff1h, NTOK, FF, E, E);
    hg0<<<dim3(E / 128, NTOK / 128, 4), 256, HSM>>>(
        ff1h, w2, lin2_b, nullptr, nullptr, pff2, nullptr, NTOK, E, FF, FF / 4);

    // ---- out = LN(x1 + 4 partials) ----
    ln_multi<<<NTOK, 256>>>(px1, pff2, 4, (long)NTOK * E, n2_g, n2_b, out, nullptr);
}

// round 15
// speedup vs baseline: 1.0371x; 1.0371x over previous
#include <cuda_runtime.h>
#include <cuda_fp16.h>
#include <math.h>
#include <stdint.h>

#define L_SEQ 256
#define NB    4
#define H     12
#define HD    64
#define E     768
#define FF    3072
#define NTOK  (L_SEQ * NB)   // 1024
#define NHB   (NB * H)       // 48

// ---------------- fp32 scratch ----------------
__device__ float g_qp[NB*H*L_SEQ*HD];
__device__ float g_qb[NB*H*L_SEQ];
__device__ float g_scores[NB*H*L_SEQ*L_SEQ];
__device__ float g_attnout[2*NTOK*E];      // 2 split-K partials
__device__ float g_x1[NTOK*E];
__device__ float g_ff2[4*NTOK*E];          // 4 split-K partials

// ---------------- fp16 operands ----------------
__device__ __align__(16) __half g_qh[NB*H*L_SEQ*HD], g_ql[NB*H*L_SEQ*HD];   // (n,h,l,d)*0.125 hi/lo
__device__ __align__(16) __half g_kh[NB*H*L_SEQ*HD];                        // (n,h,l,d) single
__device__ __align__(16) __half g_vTh[NB*H*HD*L_SEQ];                       // (n,h,d,l) single
__device__ __align__(16) __half g_ph[NB*H*L_SEQ*L_SEQ], g_pl[NB*H*L_SEQ*L_SEQ]; // probs hi/lo
// pre-converted fp16 weights/activations
__device__ __align__(16) __half g_wqkv[3*E*E];   // [3E, E] rows: q,k,v
__device__ __align__(16) __half g_wout[E*E];
__device__ __align__(16) __half g_w1[FF*E];
__device__ __align__(16) __half g_w2[E*FF];
__device__ __align__(16) __half g_srch[NTOK*E];
__device__ __align__(16) __half g_x1h[NTOK*E];
__device__ __align__(16) __half g_ff1h[NTOK*FF];
__device__ __align__(16) __half g_ctxh[NTOK*E];

// =================== PTX helpers (sm_80-compatible only) ===================
__device__ __forceinline__ uint32_t smem_u32(const void* p) {
    uint32_t a;
    asm("{ .reg .u64 t; cvta.to.shared.u64 t, %1; cvt.u32.u64 %0, t; }" : "=r"(a) : "l"(p));
    return a;
}
__device__ __forceinline__ void cp16(uint32_t dst, const void* src) {
    asm volatile("cp.async.cg.shared.global [%0], [%1], 16;\n" :: "r"(dst), "l"(src));
}
__device__ __forceinline__ void ldm4(uint32_t* r, uint32_t a) {
    asm volatile("ldmatrix.sync.aligned.m8n8.x4.shared.b16 {%0,%1,%2,%3}, [%4];"
                 : "=r"(r[0]), "=r"(r[1]), "=r"(r[2]), "=r"(r[3]) : "r"(a));
}
__device__ __forceinline__ void mma16816(float* d, const uint32_t* a, uint32_t b0, uint32_t b1) {
    asm volatile(
        "mma.sync.aligned.m16n8k16.row.col.f32.f16.f16.f32 "
        "{%0,%1,%2,%3}, {%4,%5,%6,%7}, {%8,%9}, {%0,%1,%2,%3};"
        : "+f"(d[0]), "+f"(d[1]), "+f"(d[2]), "+f"(d[3])
        : "r"(a[0]), "r"(a[1]), "r"(a[2]), "r"(a[3]), "r"(b0), "r"(b1));
}
__device__ __forceinline__ void pack4(float4 x, uint2& h) {
    __half2 hh0(__float2half(x.x), __float2half(x.y));
    __half2 hh1(__float2half(x.z), __float2half(x.w));
    h.x = *(uint32_t*)&hh0; h.y = *(uint32_t*)&hh1;
}
__device__ __forceinline__ void split1(float v, __half& h, __half& l) {
    h = __float2half(v);
    l = __float2half(v - __half2float(h));
}

// =================== single-launch fp32 -> fp16 convert (7 segments) ======
struct CvtArgs {
    const float4* src[7];
    uint2* dst[7];
    int start[8];   // prefix sums in float4 units; start[7] = total
};
__global__ void cvt_all(CvtArgs a)
{
    int i = blockIdx.x * blockDim.x + threadIdx.x;
    if (i >= a.start[7]) return;
    int seg = 0;
#pragma unroll
    for (int k = 1; k < 7; k++) seg += (i >= a.start[k]);
    int j = i - a.start[seg];
    uint2 h;
    pack4(a.src[seg][j], h);
    a.dst[seg][j] = h;
}

// ============ fp16-operand GEMM (cp.async 3-stage, 1 sync/iter) ===========
// A[M,K], B[N,K] fp16 row-major. 128x128 tile, BK=32, 8 warps.
// MODE 0: fp32 -> C + kz*M*N (bias on kz==0 if b0)
// MODE 1: bias+GELU -> fp16 C16
// MODE 2: QKV scatter (B = [3E,E] concat; b0/b1/b2 biases)
#define SA 40
#define HTILE (128 * SA * 2)            // 10240
#define HSTG  (2 * HTILE)               // 20480
#define HSM   (3 * HSTG)                // 61440

template<int MODE>
__global__ void __launch_bounds__(256, 1) hgemm(
    const __half* __restrict__ A, const __half* __restrict__ B,
    const float* __restrict__ b0, const float* __restrict__ b1, const float* __restrict__ b2,
    float* __restrict__ C, __half* __restrict__ C16,
    int M, int N, int K, int klen)
{
    extern __shared__ char smem[];
    const uint32_t sb = smem_u32(smem);
    const int tid = threadIdx.x;
    const int lane = tid & 31, wid = tid >> 5;
    const int wm = wid & 3, wn = wid >> 2;
    const int row0 = blockIdx.y * 128, col0 = blockIdx.x * 128;
    const int kz = blockIdx.z;
    const int koff = kz * klen;

    float acc[2][8][4];
#pragma unroll
    for (int i = 0; i < 2; i++)
#pragma unroll
        for (int j = 0; j < 8; j++)
#pragma unroll
            for (int r = 0; r < 4; r++) acc[i][j][r] = 0.f;

    const int niter = klen >> 5;

    auto load = [&](int it, int s) {
        const int kk = koff + it * 32;
#pragma unroll
        for (int u = 0; u < 2; u++) {
            int e = tid + u * 256;               // 0..511
            int rr = e >> 2, cc = e & 3;
            uint32_t off = (uint32_t)((rr * SA + cc * 8) * 2);
            cp16(sb + (uint32_t)(s * HSTG) + off, A + (long)(row0 + rr) * K + kk + cc * 8);
            cp16(sb + (uint32_t)(s * HSTG) + HTILE + off, B + (long)(col0 + rr) * K + kk + cc * 8);
        }
        asm volatile("cp.async.commit_group;" ::: "memory");
    };
    auto compute = [&](int s) {
        const uint32_t base = sb + (uint32_t)(s * HSTG);
#pragma unroll
        for (int ks = 0; ks < 2; ks++) {
            const uint32_t kcol = (uint32_t)((ks * 16 + (lane >> 4) * 8) * 2);
            uint32_t ah[2][4];
            const uint32_t arow = (uint32_t)(wm * 32 + (lane & 15));
#pragma unroll
            for (int t = 0; t < 2; t++) {
                uint32_t off = ((arow + t * 16) * SA) * 2 + kcol;
                ldm4(ah[t], base + off);
            }
            uint32_t bh[4][4];
            const uint32_t brow = (uint32_t)(wn * 64 + (lane & 15));
#pragma unroll
            for (int u = 0; u < 4; u++) {
                uint32_t off = ((brow + u * 16) * SA) * 2 + kcol;
                ldm4(bh[u], base + HTILE + off);
            }
#pragma unroll
            for (int mt = 0; mt < 2; mt++)
#pragma unroll
                for (int nt = 0; nt < 8; nt++) {
                    int u = nt >> 1, p = nt & 1;
                    mma16816(acc[mt][nt], ah[mt], bh[u][p], bh[u][p + 2]);
                }
        }
    };

    load(0, 0);
    int s = 0, snext = 1;
    for (int it = 0; it < niter; it++) {
        if (it + 1 < niter) {
            load(it + 1, snext);
            asm volatile("cp.async.wait_group 1;" ::: "memory");
        } else {
            asm volatile("cp.async.wait_group 0;" ::: "memory");
        }
        __syncthreads();
        compute(s);
        s = snext;
        snext = (snext == 2) ? 0 : snext + 1;
    }

    const int rl = lane >> 2, cl = (lane & 3) * 2;
#pragma unroll
    for (int mt = 0; mt < 2; mt++) {
#pragma unroll
        for (int g = 0; g < 2; g++) {
            const int m = row0 + wm * 32 + mt * 16 + g * 8 + rl;
#pragma unroll
            for (int nt = 0; nt < 8; nt++) {
                const int n = col0 + wn * 64 + nt * 8 + cl;
                float v0 = acc[mt][nt][2 * g];
                float v1 = acc[mt][nt][2 * g + 1];
                if (MODE == 0) {
                    if (b0 && kz == 0) { v0 += b0[n]; v1 += b0[n + 1]; }
                    *(float2*)(C + (long)kz * M * N + (long)m * N + n) = make_float2(v0, v1);
                } else if (MODE == 1) {
                    v0 += b0[n]; v1 += b0[n + 1];
                    v0 = 0.5f * v0 * (1.0f + erff(v0 * 0.70710678118654752f));
                    v1 = 0.5f * v1 * (1.0f + erff(v1 * 0.70710678118654752f));
                    *(__half2*)(C16 + (long)m * N + n) =
                        __half2(__float2half(v0), __float2half(v1));
                } else { // MODE 2: QKV scatter -> fp16 operand layouts
                    const int l = m >> 2, nbb = m & 3;
#pragma unroll
                    for (int q = 0; q < 2; q++) {
                        int gcol = n + q;
                        float v = q ? v1 : v0;
                        int seg = gcol / E;
                        int cc = gcol - seg * E;
                        int hh = cc >> 6, dd = cc & 63;
                        if (seg == 0) {
                            __half hb, lb;
                            split1((v + b0[cc]) * 0.125f, hb, lb);
                            long idx = (((long)(nbb * H + hh)) * L_SEQ + l) * HD + dd;
                            g_qh[idx] = hb; g_ql[idx] = lb;
                        } else if (seg == 1) {
                            long idx = (((long)(nbb * H + hh)) * L_SEQ + l) * HD + dd;
                            g_kh[idx] = __float2half(v + b1[cc]);
                        } else {
                            long idx = (((long)(nbb * H + hh)) * HD + dd) * L_SEQ + l;
                            g_vTh[idx] = __float2half(v + b2[cc]);
                        }
                    }
                }
            }
        }
    }
}

// ======= pre-split fp16 batched GEMM (attention): A hi/lo × B single ======
// 3-stage cp.async rotation, 1 sync/iter.
// MODE 0: scores fp32 -> C ; MODE 1: ctx -> fp16 C16 (scattered (l,n,e))
template<int TM, int TN, int NWM, int MODE>
__global__ void __launch_bounds__(256, 1) pgemm(
    const __half* __restrict__ Ah, const __half* __restrict__ Al,
    const __half* __restrict__ Bh,
    float* __restrict__ C, __half* __restrict__ C16, int K, long sA, long sB)
{
    constexpr int TILE_A = TM * SA * 2;
    constexpr int TILE_B = TN * SA * 2;
    constexpr int STG = 2 * TILE_A + TILE_B;
    constexpr int O_AH = 0, O_AL = TILE_A, O_BH = 2 * TILE_A;

    extern __shared__ char smem[];
    const uint32_t sb = smem_u32(smem);
    const int tid = threadIdx.x;
    const int lane = tid & 31, wid = tid >> 5;
    const int wm = wid % NWM, wn = wid / NWM;
    const int row0 = blockIdx.y * TM, col0 = blockIdx.x * TN;
    const int bz = blockIdx.z;

    const __half* pAh = Ah + (long)bz * sA;
    const __half* pAl = Al + (long)bz * sA;
    const __half* pBh = Bh + (long)bz * sB;

    float acc[2][8][4];
#pragma unroll
    for (int i = 0; i < 2; i++)
#pragma unroll
        for (int j = 0; j < 8; j++)
#pragma unroll
            for (int r = 0; r < 4; r++) acc[i][j][r] = 0.f;

    const int niter = K >> 5;

    auto load = [&](int it, int s) {
        const int koff = it * 32;
        for (int e = tid; e < TM * 4; e += 256) {
            int rr = e >> 2, cc = e & 3;
            uint32_t off = (uint32_t)((rr * SA + cc * 8) * 2);
            long go = (long)(row0 + rr) * K + koff + cc * 8;
            cp16(sb + (uint32_t)(s * STG) + O_AH + off, pAh + go);
            cp16(sb + (uint32_t)(s * STG) + O_AL + off, pAl + go);
        }
        for (int e = tid; e < TN * 4; e += 256) {
            int rr = e >> 2, cc = e & 3;
            uint32_t off = (uint32_t)((rr * SA + cc * 8) * 2);
            long go = (long)(col0 + rr) * K + koff + cc * 8;
            cp16(sb + (uint32_t)(s * STG) + O_BH + off, pBh + go);
        }
        asm volatile("cp.async.commit_group;" ::: "memory");
    };
    auto compute = [&](int s) {
        const uint32_t base = sb + (uint32_t)(s * STG);
#pragma unroll
        for (int ks = 0; ks < 2; ks++) {
            const uint32_t kcol = (uint32_t)((ks * 16 + (lane >> 4) * 8) * 2);
            uint32_t ah[2][4], al[2][4];
            const uint32_t arow = (uint32_t)(wm * 32 + (lane & 15));
#pragma unroll
            for (int t = 0; t < 2; t++) {
                uint32_t off = ((arow + t * 16) * SA) * 2 + kcol;
                ldm4(ah[t], base + O_AH + off);
                ldm4(al[t], base + O_AL + off);
            }
            uint32_t bh[4][4];
            const uint32_t brow = (uint32_t)(wn * 64 + (lane & 15));
#pragma unroll
            for (int u = 0; u < 4; u++) {
                uint32_t off = ((brow + u * 16) * SA) * 2 + kcol;
                ldm4(bh[u], base + O_BH + off);
            }
#pragma unroll
            for (int mt = 0; mt < 2; mt++)
#pragma unroll
                for (int nt = 0; nt < 8; nt++) {
                    int u = nt >> 1, p = nt & 1;
                    mma16816(acc[mt][nt], ah[mt], bh[u][p], bh[u][p + 2]);
                    mma16816(acc[mt][nt], al[mt], bh[u][p], bh[u][p + 2]);
                }
        }
    };

    load(0, 0);
    int s = 0, snext = 1;
    for (int it = 0; it < niter; it++) {
        if (it + 1 < niter) {
            load(it + 1, snext);
            asm volatile("cp.async.wait_group 1;" ::: "memory");
        } else {
            asm volatile("cp.async.wait_group 0;" ::: "memory");
        }
        __syncthreads();
        compute(s);
        s = snext;
        snext = (snext == 2) ? 0 : snext + 1;
    }

    const int rl = lane >> 2, cl = (lane & 3) * 2;
#pragma unroll
    for (int mt = 0; mt < 2; mt++) {
#pragma unroll
        for (int g = 0; g < 2; g++) {
            const int m = row0 + wm * 32 + mt * 16 + g * 8 + rl;
#pragma unroll
            for (int nt = 0; nt < 8; nt++) {
                const int n = col0 + wn * 64 + nt * 8 + cl;
                float v0 = acc[mt][nt][2 * g];
                float v1 = acc[mt][nt][2 * g + 1];
                if (MODE == 0) {
                    *(float2*)(C + (long)bz * L_SEQ * L_SEQ + (long)m * L_SEQ + n) =
                        make_float2(v0, v1);
                } else {
                    const int nb = bz / H, hh = bz % H;
                    *(__half2*)(C16 + ((long)m * NB + nb) * E + hh * HD + n) =
                        __half2(__float2half(v0), __float2half(v1));
                }
            }
        }
    }
}

// ---- qp[n,h,i,c] = sum_d q[n,h,i,d]*p_w[h*64+d,c]; qb = q . p_b ---------
__global__ void qp2_kernel(const float* __restrict__ p_w, const float* __restrict__ p_b)
{
    const int h = blockIdx.y;
    const int m0 = blockIdx.x * 64;
    __shared__ float w[64][65];
    __shared__ float qs[64][65];
    __shared__ float pb[64];
    const int tid = threadIdx.x;          // 256
    for (int e = tid; e < 4096; e += 256) {
        int d = e >> 6, c = e & 63;
        w[d][c] = p_w[(h * 64 + d) * 64 + c];
    }
    if (tid < 64) pb[tid] = p_b[h * 64 + tid];
    for (int e = tid; e < 4096; e += 256) {
        int r = e >> 6, d = e & 63;
        int mg = m0 + r;
        int n = mg >> 8, l = mg & 255;
        long idx = (((long)(n * H + h)) * L_SEQ + l) * HD + d;
        qs[r][d] = __half2float(g_qh[idx]) + __half2float(g_ql[idx]);
    }
    __syncthreads();

    const int rr = tid >> 2, cg = tid & 3;
    float acc[16];
#pragma unroll
    for (int c = 0; c < 16; c++) acc[c] = 0.f;
#pragma unroll
    for (int d = 0; d < 64; d++) {
        float qv = qs[rr][d];
#pragma unroll
        for (int c = 0; c < 16; c++) acc[c] += qv * w[d][cg * 16 + c];
    }
    const int mg = m0 + rr;
    const int n = mg >> 8, l = mg & 255;
    const long base = (((long)(n * H + h)) * L_SEQ + l) * HD;
#pragma unroll
    for (int c = 0; c < 16; c++) g_qp[base + cg * 16 + c] = acc[c];
    if (cg == 0) {
        float sb = 0.f;
#pragma unroll
        for (int d = 0; d < 64; d++) sb += qs[rr][d] * pb[d];
        g_qb[((long)n * H + h) * L_SEQ + l] = sb;
    }
}

// ---- cpm_fused: per (n,i): full score row (qk + qp@pos^T + qb), softmax,
//      write probs hi/lo.
#define CSA 72   // fp16 elements per row (64 + 8 pad)
__global__ void __launch_bounds__(256) cpm_kernel(const float* __restrict__ pos)
{
    __shared__ __align__(16) __half sAh[16 * CSA];
    __shared__ __align__(16) __half sAl[16 * CSA];
    __shared__ __align__(16) __half sB[L_SEQ * CSA];
    __shared__ float qbs[12];
    __shared__ float wred[8][12];
    __shared__ float rowv[12];

    const int b = blockIdx.x;            // n*L + i
    const int n = b >> 8, i = b & 255;
    const int tid = threadIdx.x;
    const int lane = tid & 31, wid = tid >> 5;

    for (int e = tid; e < 1024; e += 256) {
        int h = e >> 6, c = e & 63;
        float v = (h < 12) ? g_qp[(((long)(n * H + h)) * L_SEQ + i) * HD + c] : 0.f;
        __half hb, lb;
        split1(v, hb, lb);
        sAh[h * CSA + c] = hb;
        sAl[h * CSA + c] = lb;
    }
    if (tid < 12) qbs[tid] = g_qb[((long)n * H + tid) * L_SEQ + i];

    const float4* pr = (const float4*)(pos + (((long)n * L_SEQ + i) * L_SEQ) * 64);
#pragma unroll 8
    for (int u = 0; u < 16; u++) {
        int e = tid + u * 256;
        int rr = e >> 4, cc = e & 15;
        float4 v = pr[e];
        uint2 h;
        pack4(v, h);
        *(uint2*)&sB[rr * CSA + cc * 4] = h;
    }
    __syncthreads();

    const uint32_t aB = smem_u32(sAh), aL = smem_u32(sAl), bB = smem_u32(sB);
    const int n0 = wid * 32;

    float acc[4][4];
#pragma unroll
    for (int j = 0; j < 4; j++)
#pragma unroll
        for (int r = 0; r < 4; r++) acc[j][r] = 0.f;

#pragma unroll
    for (int ks = 0; ks < 4; ks++) {
        const uint32_t kcol = (uint32_t)((ks * 16 + (lane >> 4) * 8) * 2);
        uint32_t ah[4], al[4];
        {
            uint32_t off = ((uint32_t)(lane & 15) * CSA) * 2 + kcol;
            ldm4(ah, aB + off);
            ldm4(al, aL + off);
        }
        uint32_t bh[2][4];
#pragma unroll
        for (int t = 0; t < 2; t++) {
            uint32_t off = ((uint32_t)(n0 + (lane & 15) + t * 16) * CSA) * 2 + kcol;
            ldm4(bh[t], bB + off);
        }
#pragma unroll
        for (int nt = 0; nt < 4; nt++) {
            int u = nt >> 1, p = nt & 1;
            mma16816(acc[nt], ah, bh[u][p], bh[u][p + 2]);
            mma16816(acc[nt], al, bh[u][p], bh[u][p + 2]);
        }
    }

    const int rl = lane >> 2, cl = (lane & 3) * 2;
    float sc[2][8];
#pragma unroll
    for (int g = 0; g < 2; g++) {
        const int m = g * 8 + rl;
        if (m < 12) {
            const float qb = qbs[m];
            const float* srow = g_scores + ((((long)n * H + m) * L_SEQ + i) * L_SEQ);
#pragma unroll
            for (int nt = 0; nt < 4; nt++) {
                const int j = n0 + nt * 8 + cl;
                float2 qk = *(const float2*)(srow + j);
                sc[g][2 * nt]     = qk.x + acc[nt][2 * g]     + qb;
                sc[g][2 * nt + 1] = qk.y + acc[nt][2 * g + 1] + qb;
            }
        } else {
#pragma unroll
            for (int c = 0; c < 8; c++) sc[g][c] = -1e30f;
        }
    }

    float mymax[2];
#pragma unroll
    for (int g = 0; g < 2; g++) {
        float m = sc[g][0];
#pragma unroll
        for (int c = 1; c < 8; c++) m = fmaxf(m, sc[g][c]);
        m = fmaxf(m, __shfl_xor_sync(0xffffffffu, m, 1));
        m = fmaxf(m, __shfl_xor_sync(0xffffffffu, m, 2));
        mymax[g] = m;
    }
    if ((lane & 3) == 0) {
        wred[wid][rl] = mymax[0];
        if (8 + rl < 12) wred[wid][8 + rl] = mymax[1];
    }
    __syncthreads();
    if (tid < 12) {
        float m = wred[0][tid];
#pragma unroll
        for (int w = 1; w < 8; w++) m = fmaxf(m, wred[w][tid]);
        rowv[tid] = m;
    }
    __syncthreads();
    float rmax[2];
    rmax[0] = rowv[rl];
    rmax[1] = (8 + rl < 12) ? rowv[8 + rl] : 0.f;
    __syncthreads();

    float mysum[2];
#pragma unroll
    for (int g = 0; g < 2; g++) {
        float s = 0.f;
#pragma unroll
        for (int c = 0; c < 8; c++) {
            float e = __expf(sc[g][c] - rmax[g]);
            sc[g][c] = e;
            s += e;
        }
        s += __shfl_xor_sync(0xffffffffu, s, 1);
        s += __shfl_xor_sync(0xffffffffu, s, 2);
        mysum[g] = s;
    }
    if ((lane & 3) == 0) {
        wred[wid][rl] = mysum[0];
        if (8 + rl < 12) wred[wid][8 + rl] = mysum[1];
    }
    __syncthreads();
    if (tid < 12) {
        float s = 0.f;
#pragma unroll
        for (int w = 0; w < 8; w++) s += wred[w][tid];
        rowv[tid] = 1.f / s;
    }
    __syncthreads();
    float rinv[2];
    rinv[0] = rowv[rl];
    rinv[1] = (8 + rl < 12) ? rowv[8 + rl] : 0.f;

#pragma unroll
    for (int g = 0; g < 2; g++) {
        const int m = g * 8 + rl;
        if (m < 12) {
            const long rbase = (((long)n * H + m) * L_SEQ + i) * L_SEQ;
#pragma unroll
            for (int nt = 0; nt < 4; nt++) {
                const int j = n0 + nt * 8 + cl;
                float p0 = sc[g][2 * nt] * rinv[g];
                float p1 = sc[g][2 * nt + 1] * rinv[g];
                __half h0, l0, h1, l1;
                split1(p0, h0, l0);
                split1(p1, h1, l1);
                *(__half2*)(g_ph + rbase + j) = __half2(h0, h1);
                *(__half2*)(g_pl + rbase + j) = __half2(l0, l1);
            }
        }
    }
}

// ---- out = LayerNorm(a + sum partials); optional fp16 copy ---------------
__global__ void ln_multi(const float* __restrict__ a, const float* __restrict__ p,
                         int nparts, long pstride,
                         const float* __restrict__ gamma, const float* __restrict__ beta,
                         float* __restrict__ out, __half* __restrict__ out16)
{
    const int row = blockIdx.x;
    const int t = threadIdx.x;
    __shared__ float rs[8], rq[8];
    float v[3];
    float s = 0.f, s2 = 0.f;
#pragma unroll
    for (int u = 0; u < 3; u++) {
        long idx = (long)row * E + t + u * 256;
        float x = a[idx];
        for (int z = 0; z < nparts; z++) x += p[z * pstride + idx];
        v[u] = x; s += x; s2 += x * x;
    }
#pragma unroll
    for (int o = 16; o > 0; o >>= 1) {
        s  += __shfl_xor_sync(0xffffffffu, s, o);
        s2 += __shfl_xor_sync(0xffffffffu, s2, o);
    }
    if ((t & 31) == 0) { rs[t >> 5] = s; rq[t >> 5] = s2; }
    __syncthreads();
    if (t < 32) {
        float a1 = (t < 8) ? rs[t] : 0.f;
        float a2 = (t < 8) ? rq[t] : 0.f;
#pragma unroll
        for (int o = 4; o > 0; o >>= 1) {
            a1 += __shfl_xor_sync(0xffffffffu, a1, o);
            a2 += __shfl_xor_sync(0xffffffffu, a2, o);
        }
        if (t == 0) { rs[0] = a1; rq[0] = a2; }
    }
    __syncthreads();
    float mean = rs[0] * (1.f / 768.f);
    float var  = rq[0] * (1.f / 768.f) - mean * mean;
    float r = rsqrtf(var + 1e-5f);
#pragma unroll
    for (int u = 0; u < 3; u++) {
        int c = t + u * 256;
        float o = (v[u] - mean) * r * gamma[c] + beta[c];
        out[(long)row * E + c] = o;
        if (out16) out16[(long)row * E + c] = __float2half(o);
    }
}

// =================== host launcher ===================
extern "C" void kernel_launch(void* const* d_in, const int* in_sizes, int n_in,
                              void* d_out, int out_size)
{
    const float* src    = (const float*)d_in[0];
    const float* pos    = (const float*)d_in[1];
    const float* q_w    = (const float*)d_in[2];
    const float* q_b    = (const float*)d_in[3];
    const float* k_w    = (const float*)d_in[4];
    const float* k_b    = (const float*)d_in[5];
    const float* v_w    = (const float*)d_in[6];
    const float* v_b    = (const float*)d_in[7];
    const float* p_w    = (const float*)d_in[8];
    const float* p_b    = (const float*)d_in[9];
    const float* out_w  = (const float*)d_in[10];
    const float* out_b  = (const float*)d_in[11];
    const float* lin1_w = (const float*)d_in[12];
    const float* lin1_b = (const float*)d_in[13];
    const float* lin2_w = (const float*)d_in[14];
    const float* lin2_b = (const float*)d_in[15];
    const float* n1_g   = (const float*)d_in[16];
    const float* n1_b   = (const float*)d_in[17];
    const float* n2_g   = (const float*)d_in[18];
    const float* n2_b   = (const float*)d_in[19];
    float* out = (float*)d_out;

    auto hg0 = hgemm<0>; auto hg1 = hgemm<1>; auto hg2 = hgemm<2>;
    auto pg_scores = pgemm<128, 128, 4, 0>;
    auto pg_ctx    = pgemm<256, 64, 8, 1>;
    const int smem_scores = 3 * (2 * 128 * SA * 2 + 128 * SA * 2);          // 92160
    const int smem_ctx    = 3 * (2 * 256 * SA * 2 + 64 * SA * 2);           // 138240
    cudaFuncSetAttribute(hg0, cudaFuncAttributeMaxDynamicSharedMemorySize, HSM);
    cudaFuncSetAttribute(hg1, cudaFuncAttributeMaxDynamicSharedMemorySize, HSM);
    cudaFuncSetAttribute(hg2, cudaFuncAttributeMaxDynamicSharedMemorySize, HSM);
    cudaFuncSetAttribute(pg_scores, cudaFuncAttributeMaxDynamicSharedMemorySize, smem_scores);
    cudaFuncSetAttribute(pg_ctx, cudaFuncAttributeMaxDynamicSharedMemorySize, smem_ctx);

    float *pscores, *pattn, *px1, *pff2;
    cudaGetSymbolAddress((void**)&pscores, g_scores);
    cudaGetSymbolAddress((void**)&pattn,   g_attnout);
    cudaGetSymbolAddress((void**)&px1,     g_x1);
    cudaGetSymbolAddress((void**)&pff2,    g_ff2);

    __half *qh, *ql, *kh, *vTh, *ph, *pl;
    __half *wqkv, *wout, *w1, *w2, *srch, *x1h, *ff1h, *ctxh;
    cudaGetSymbolAddress((void**)&qh,   g_qh);  cudaGetSymbolAddress((void**)&ql, g_ql);
    cudaGetSymbolAddress((void**)&kh,   g_kh);
    cudaGetSymbolAddress((void**)&vTh,  g_vTh);
    cudaGetSymbolAddress((void**)&ph,   g_ph);  cudaGetSymbolAddress((void**)&pl, g_pl);
    cudaGetSymbolAddress((void**)&wqkv, g_wqkv);
    cudaGetSymbolAddress((void**)&wout, g_wout);
    cudaGetSymbolAddress((void**)&w1,   g_w1);
    cudaGetSymbolAddress((void**)&w2,   g_w2);
    cudaGetSymbolAddress((void**)&srch, g_srch);
    cudaGetSymbolAddress((void**)&x1h,  g_x1h);
    cudaGetSymbolAddress((void**)&ff1h, g_ff1h);
    cudaGetSymbolAddress((void**)&ctxh, g_ctxh);

    // ---- single-launch fp32 -> fp16 converts (7 segments) ----
    {
        CvtArgs a;
        const float* srcs[7]  = { q_w, k_w, v_w, out_w, lin1_w, lin2_w, src };
        __half* dsts[7] = { wqkv, wqkv + E * E, wqkv + 2 * E * E, wout, w1, w2, srch };
        int sizes[7] = { E*E, E*E, E*E, E*E, FF*E, E*FF, NTOK*E };
        int acc = 0;
        for (int k = 0; k < 7; k++) {
            a.src[k] = (const float4*)srcs[k];
            a.dst[k] = (uint2*)dsts[k];
            a.start[k] = acc;
            acc += sizes[k] / 4;
        }
        a.start[7] = acc;
        cvt_all<<<(acc + 255) / 256, 256>>>(a);
    }

    // ---- fused QKV projection ----
    hg2<<<dim3(3 * E / 128, NTOK / 128, 1), 256, HSM>>>(
        srch, wqkv, q_b, k_b, v_b, nullptr, nullptr, NTOK, 3 * E, E, E);

    // ---- attention ----
    qp2_kernel<<<dim3(16, 12), 256>>>(p_w, p_b);
    pg_scores<<<dim3(2, 2, NHB), 256, smem_scores>>>(
        qh, ql, kh, pscores, nullptr, HD, (long)L_SEQ * HD, (long)L_SEQ * HD);
    cpm_kernel<<<NB * L_SEQ, 256>>>(pos);     // fused pos-scores + softmax
    pg_ctx<<<dim3(1, 1, NHB), 256, smem_ctx>>>(
        ph, pl, vTh, nullptr, ctxh, L_SEQ, (long)L_SEQ * L_SEQ, (long)HD * L_SEQ);

    // ---- output projection (split-K=2) ----
    hg0<<<dim3(E / 128, NTOK / 128, 2), 256, HSM>>>(
        ctxh, wout, out_b, nullptr, nullptr, pattn, nullptr, NTOK, E, E, E / 2);

    // ---- x1 = LN(src + partials) ----
    ln_multi<<<NTOK, 256>>>(src, pattn, 2, (long)NTOK * E, n1_g, n1_b, px1, x1h);

    // ---- FFN ----
    hg1<<<dim3(FF / 128, NTOK / 128, 1), 256, HSM>>>(
        x1h, w1, lin1_b, nullptr, nullptr, nullptr, ff1h, NTOK, FF, E, E);
    hg0<<<dim3(E / 128, NTOK / 128, 4), 256, HSM>>>(
        ff1h, w2, lin2_b, nullptr, nullptr, pff2, nullptr, NTOK, E, FF, FF / 4);

    // ---- out = LN(x1 + 4 partials) ----
    ln_multi<<<NTOK, 256>>>(px1, pff2, 4, (long)NTOK * E, n2_g, n2_b, out, nullptr);
}

// round 16
// speedup vs baseline: 1.0604x; 1.0224x over previous
#include <cuda_runtime.h>
#include <cuda_fp16.h>
#include <math.h>
#include <stdint.h>

#define L_SEQ 256
#define NB    4
#define H     12
#define HD    64
#define E     768
#define FF    3072
#define NTOK  (L_SEQ * NB)   // 1024
#define NHB   (NB * H)       // 48

// ---------------- fp32 scratch ----------------
__device__ float g_qp[NB*H*L_SEQ*HD];
__device__ float g_qb[NB*H*L_SEQ];
__device__ float g_scores[NB*H*L_SEQ*L_SEQ];
__device__ float g_attnout[2*NTOK*E];      // 2 split-K partials
__device__ float g_x1[NTOK*E];
__device__ float g_ff2[4*NTOK*E];          // 4 split-K partials

// ---------------- fp16 operands ----------------
__device__ __align__(16) __half g_qh[NB*H*L_SEQ*HD], g_ql[NB*H*L_SEQ*HD];   // (n,h,l,d)*0.125 hi/lo
__device__ __align__(16) __half g_kh[NB*H*L_SEQ*HD];                        // (n,h,l,d) single
__device__ __align__(16) __half g_vTh[NB*H*HD*L_SEQ];                       // (n,h,d,l) single
__device__ __align__(16) __half g_ph[NB*H*L_SEQ*L_SEQ], g_pl[NB*H*L_SEQ*L_SEQ]; // probs hi/lo
// pre-converted fp16 weights/activations
__device__ __align__(16) __half g_wqkv[3*E*E];   // [3E, E] rows: q,k,v
__device__ __align__(16) __half g_wout[E*E];
__device__ __align__(16) __half g_w1[FF*E];
__device__ __align__(16) __half g_w2[E*FF];
__device__ __align__(16) __half g_srch[NTOK*E];
__device__ __align__(16) __half g_x1h[NTOK*E];
__device__ __align__(16) __half g_ff1h[NTOK*FF];
__device__ __align__(16) __half g_ctxh[NTOK*E];

// =================== PTX helpers (sm_80-compatible only) ===================
__device__ __forceinline__ uint32_t smem_u32(const void* p) {
    uint32_t a;
    asm("{ .reg .u64 t; cvta.to.shared.u64 t, %1; cvt.u32.u64 %0, t; }" : "=r"(a) : "l"(p));
    return a;
}
__device__ __forceinline__ void cp16(uint32_t dst, const void* src) {
    asm volatile("cp.async.cg.shared.global [%0], [%1], 16;\n" :: "r"(dst), "l"(src));
}
__device__ __forceinline__ void ldm4(uint32_t* r, uint32_t a) {
    asm volatile("ldmatrix.sync.aligned.m8n8.x4.shared.b16 {%0,%1,%2,%3}, [%4];"
                 : "=r"(r[0]), "=r"(r[1]), "=r"(r[2]), "=r"(r[3]) : "r"(a));
}
__device__ __forceinline__ void mma16816(float* d, const uint32_t* a, uint32_t b0, uint32_t b1) {
    asm volatile(
        "mma.sync.aligned.m16n8k16.row.col.f32.f16.f16.f32 "
        "{%0,%1,%2,%3}, {%4,%5,%6,%7}, {%8,%9}, {%0,%1,%2,%3};"
        : "+f"(d[0]), "+f"(d[1]), "+f"(d[2]), "+f"(d[3])
        : "r"(a[0]), "r"(a[1]), "r"(a[2]), "r"(a[3]), "r"(b0), "r"(b1));
}
__device__ __forceinline__ void pack4(float4 x, uint2& h) {
    __half2 hh0(__float2half(x.x), __float2half(x.y));
    __half2 hh1(__float2half(x.z), __float2half(x.w));
    h.x = *(uint32_t*)&hh0; h.y = *(uint32_t*)&hh1;
}
__device__ __forceinline__ void split1(float v, __half& h, __half& l) {
    h = __float2half(v);
    l = __float2half(v - __half2float(h));
}

// =================== single-launch fp32 -> fp16 convert (7 segments) ======
struct CvtArgs {
    const float4* src[7];
    uint2* dst[7];
    int start[8];   // prefix sums in float4 units; start[7] = total
};
__global__ void cvt_all(CvtArgs a)
{
    int i = blockIdx.x * blockDim.x + threadIdx.x;
    if (i >= a.start[7]) return;
    int seg = 0;
#pragma unroll
    for (int k = 1; k < 7; k++) seg += (i >= a.start[k]);
    int j = i - a.start[seg];
    uint2 h;
    pack4(a.src[seg][j], h);
    a.dst[seg][j] = h;
}

// ============ fp16-operand GEMM (cp.async 3-stage, 1 sync/iter) ===========
// A[M,K], B[N,K] fp16 row-major. 128x128 tile, BK=32, 8 warps.
// 2 CTAs/SM co-residency (regs fit under 128 now: no register staging).
// MODE 0: fp32 -> C + kz*M*N (bias on kz==0 if b0)
// MODE 1: bias+GELU -> fp16 C16
// MODE 2: QKV scatter (B = [3E,E] concat; b0/b1/b2 biases)
#define SA 40
#define HTILE (128 * SA * 2)            // 10240
#define HSTG  (2 * HTILE)               // 20480
#define HSM   (3 * HSTG)                // 61440

template<int MODE>
__global__ void __launch_bounds__(256, 2) hgemm(
    const __half* __restrict__ A, const __half* __restrict__ B,
    const float* __restrict__ b0, const float* __restrict__ b1, const float* __restrict__ b2,
    float* __restrict__ C, __half* __restrict__ C16,
    int M, int N, int K, int klen)
{
    extern __shared__ char smem[];
    const uint32_t sb = smem_u32(smem);
    const int tid = threadIdx.x;
    const int lane = tid & 31, wid = tid >> 5;
    const int wm = wid & 3, wn = wid >> 2;
    const int row0 = blockIdx.y * 128, col0 = blockIdx.x * 128;
    const int kz = blockIdx.z;
    const int koff = kz * klen;

    float acc[2][8][4];
#pragma unroll
    for (int i = 0; i < 2; i++)
#pragma unroll
        for (int j = 0; j < 8; j++)
#pragma unroll
            for (int r = 0; r < 4; r++) acc[i][j][r] = 0.f;

    const int niter = klen >> 5;

    auto load = [&](int it, int s) {
        const int kk = koff + it * 32;
#pragma unroll
        for (int u = 0; u < 2; u++) {
            int e = tid + u * 256;               // 0..511
            int rr = e >> 2, cc = e & 3;
            uint32_t off = (uint32_t)((rr * SA + cc * 8) * 2);
            cp16(sb + (uint32_t)(s * HSTG) + off, A + (long)(row0 + rr) * K + kk + cc * 8);
            cp16(sb + (uint32_t)(s * HSTG) + HTILE + off, B + (long)(col0 + rr) * K + kk + cc * 8);
        }
        asm volatile("cp.async.commit_group;" ::: "memory");
    };
    auto compute = [&](int s) {
        const uint32_t base = sb + (uint32_t)(s * HSTG);
#pragma unroll
        for (int ks = 0; ks < 2; ks++) {
            const uint32_t kcol = (uint32_t)((ks * 16 + (lane >> 4) * 8) * 2);
            uint32_t ah[2][4];
            const uint32_t arow = (uint32_t)(wm * 32 + (lane & 15));
#pragma unroll
            for (int t = 0; t < 2; t++) {
                uint32_t off = ((arow + t * 16) * SA) * 2 + kcol;
                ldm4(ah[t], base + off);
            }
            uint32_t bh[4][4];
            const uint32_t brow = (uint32_t)(wn * 64 + (lane & 15));
#pragma unroll
            for (int u = 0; u < 4; u++) {
                uint32_t off = ((brow + u * 16) * SA) * 2 + kcol;
                ldm4(bh[u], base + HTILE + off);
            }
#pragma unroll
            for (int mt = 0; mt < 2; mt++)
#pragma unroll
                for (int nt = 0; nt < 8; nt++) {
                    int u = nt >> 1, p = nt & 1;
                    mma16816(acc[mt][nt], ah[mt], bh[u][p], bh[u][p + 2]);
                }
        }
    };

    load(0, 0);
    int s = 0, snext = 1;
    for (int it = 0; it < niter; it++) {
        if (it + 1 < niter) {
            load(it + 1, snext);
            asm volatile("cp.async.wait_group 1;" ::: "memory");
        } else {
            asm volatile("cp.async.wait_group 0;" ::: "memory");
        }
        __syncthreads();
        compute(s);
        s = snext;
        snext = (snext == 2) ? 0 : snext + 1;
    }

    const int rl = lane >> 2, cl = (lane & 3) * 2;
#pragma unroll
    for (int mt = 0; mt < 2; mt++) {
#pragma unroll
        for (int g = 0; g < 2; g++) {
            const int m = row0 + wm * 32 + mt * 16 + g * 8 + rl;
#pragma unroll
            for (int nt = 0; nt < 8; nt++) {
                const int n = col0 + wn * 64 + nt * 8 + cl;
                float v0 = acc[mt][nt][2 * g];
                float v1 = acc[mt][nt][2 * g + 1];
                if (MODE == 0) {
                    if (b0 && kz == 0) { v0 += b0[n]; v1 += b0[n + 1]; }
                    *(float2*)(C + (long)kz * M * N + (long)m * N + n) = make_float2(v0, v1);
                } else if (MODE == 1) {
                    v0 += b0[n]; v1 += b0[n + 1];
                    v0 = 0.5f * v0 * (1.0f + erff(v0 * 0.70710678118654752f));
                    v1 = 0.5f * v1 * (1.0f + erff(v1 * 0.70710678118654752f));
                    *(__half2*)(C16 + (long)m * N + n) =
                        __half2(__float2half(v0), __float2half(v1));
                } else { // MODE 2: QKV scatter -> fp16 operand layouts
                    const int l = m >> 2, nbb = m & 3;
#pragma unroll
                    for (int q = 0; q < 2; q++) {
                        int gcol = n + q;
                        float v = q ? v1 : v0;
                        int seg = gcol / E;
                        int cc = gcol - seg * E;
                        int hh = cc >> 6, dd = cc & 63;
                        if (seg == 0) {
                            __half hb, lb;
                            split1((v + b0[cc]) * 0.125f, hb, lb);
                            long idx = (((long)(nbb * H + hh)) * L_SEQ + l) * HD + dd;
                            g_qh[idx] = hb; g_ql[idx] = lb;
                        } else if (seg == 1) {
                            long idx = (((long)(nbb * H + hh)) * L_SEQ + l) * HD + dd;
                            g_kh[idx] = __float2half(v + b1[cc]);
                        } else {
                            long idx = (((long)(nbb * H + hh)) * HD + dd) * L_SEQ + l;
                            g_vTh[idx] = __float2half(v + b2[cc]);
                        }
                    }
                }
            }
        }
    }
}

// ======= pre-split fp16 batched GEMM (attention): A hi/lo × B single ======
// 3-stage cp.async rotation, 1 sync/iter.
// MODE 0: scores fp32 -> C ; MODE 1: ctx -> fp16 C16 (scattered (l,n,e))
template<int TM, int TN, int NWM, int MODE>
__global__ void __launch_bounds__(256, 1) pgemm(
    const __half* __restrict__ Ah, const __half* __restrict__ Al,
    const __half* __restrict__ Bh,
    float* __restrict__ C, __half* __restrict__ C16, int K, long sA, long sB)
{
    constexpr int TILE_A = TM * SA * 2;
    constexpr int TILE_B = TN * SA * 2;
    constexpr int STG = 2 * TILE_A + TILE_B;
    constexpr int O_AH = 0, O_AL = TILE_A, O_BH = 2 * TILE_A;

    extern __shared__ char smem[];
    const uint32_t sb = smem_u32(smem);
    const int tid = threadIdx.x;
    const int lane = tid & 31, wid = tid >> 5;
    const int wm = wid % NWM, wn = wid / NWM;
    const int row0 = blockIdx.y * TM, col0 = blockIdx.x * TN;
    const int bz = blockIdx.z;

    const __half* pAh = Ah + (long)bz * sA;
    const __half* pAl = Al + (long)bz * sA;
    const __half* pBh = Bh + (long)bz * sB;

    float acc[2][8][4];
#pragma unroll
    for (int i = 0; i < 2; i++)
#pragma unroll
        for (int j = 0; j < 8; j++)
#pragma unroll
            for (int r = 0; r < 4; r++) acc[i][j][r] = 0.f;

    const int niter = K >> 5;

    auto load = [&](int it, int s) {
        const int koff = it * 32;
        for (int e = tid; e < TM * 4; e += 256) {
            int rr = e >> 2, cc = e & 3;
            uint32_t off = (uint32_t)((rr * SA + cc * 8) * 2);
            long go = (long)(row0 + rr) * K + koff + cc * 8;
            cp16(sb + (uint32_t)(s * STG) + O_AH + off, pAh + go);
            cp16(sb + (uint32_t)(s * STG) + O_AL + off, pAl + go);
        }
        for (int e = tid; e < TN * 4; e += 256) {
            int rr = e >> 2, cc = e & 3;
            uint32_t off = (uint32_t)((rr * SA + cc * 8) * 2);
            long go = (long)(col0 + rr) * K + koff + cc * 8;
            cp16(sb + (uint32_t)(s * STG) + O_BH + off, pBh + go);
        }
        asm volatile("cp.async.commit_group;" ::: "memory");
    };
    auto compute = [&](int s) {
        const uint32_t base = sb + (uint32_t)(s * STG);
#pragma unroll
        for (int ks = 0; ks < 2; ks++) {
            const uint32_t kcol = (uint32_t)((ks * 16 + (lane >> 4) * 8) * 2);
            uint32_t ah[2][4], al[2][4];
            const uint32_t arow = (uint32_t)(wm * 32 + (lane & 15));
#pragma unroll
            for (int t = 0; t < 2; t++) {
                uint32_t off = ((arow + t * 16) * SA) * 2 + kcol;
                ldm4(ah[t], base + O_AH + off);
                ldm4(al[t], base + O_AL + off);
            }
            uint32_t bh[4][4];
            const uint32_t brow = (uint32_t)(wn * 64 + (lane & 15));
#pragma unroll
            for (int u = 0; u < 4; u++) {
                uint32_t off = ((brow + u * 16) * SA) * 2 + kcol;
                ldm4(bh[u], base + O_BH + off);
            }
#pragma unroll
            for (int mt = 0; mt < 2; mt++)
#pragma unroll
                for (int nt = 0; nt < 8; nt++) {
                    int u = nt >> 1, p = nt & 1;
                    mma16816(acc[mt][nt], ah[mt], bh[u][p], bh[u][p + 2]);
                    mma16816(acc[mt][nt], al[mt], bh[u][p], bh[u][p + 2]);
                }
        }
    };

    load(0, 0);
    int s = 0, snext = 1;
    for (int it = 0; it < niter; it++) {
        if (it + 1 < niter) {
            load(it + 1, snext);
            asm volatile("cp.async.wait_group 1;" ::: "memory");
        } else {
            asm volatile("cp.async.wait_group 0;" ::: "memory");
        }
        __syncthreads();
        compute(s);
        s = snext;
        snext = (snext == 2) ? 0 : snext + 1;
    }

    const int rl = lane >> 2, cl = (lane & 3) * 2;
#pragma unroll
    for (int mt = 0; mt < 2; mt++) {
#pragma unroll
        for (int g = 0; g < 2; g++) {
            const int m = row0 + wm * 32 + mt * 16 + g * 8 + rl;
#pragma unroll
            for (int nt = 0; nt < 8; nt++) {
                const int n = col0 + wn * 64 + nt * 8 + cl;
                float v0 = acc[mt][nt][2 * g];
                float v1 = acc[mt][nt][2 * g + 1];
                if (MODE == 0) {
                    *(float2*)(C + (long)bz * L_SEQ * L_SEQ + (long)m * L_SEQ + n) =
                        make_float2(v0, v1);
                } else {
                    const int nb = bz / H, hh = bz % H;
                    *(__half2*)(C16 + ((long)m * NB + nb) * E + hh * HD + n) =
                        __half2(__float2half(v0), __float2half(v1));
                }
            }
        }
    }
}

// ---- qp[n,h,i,c] = sum_d q[n,h,i,d]*p_w[h*64+d,c]; qb = q . p_b ---------
__global__ void qp2_kernel(const float* __restrict__ p_w, const float* __restrict__ p_b)
{
    const int h = blockIdx.y;
    const int m0 = blockIdx.x * 64;
    __shared__ float w[64][65];
    __shared__ float qs[64][65];
    __shared__ float pb[64];
    const int tid = threadIdx.x;          // 256
    for (int e = tid; e < 4096; e += 256) {
        int d = e >> 6, c = e & 63;
        w[d][c] = p_w[(h * 64 + d) * 64 + c];
    }
    if (tid < 64) pb[tid] = p_b[h * 64 + tid];
    for (int e = tid; e < 4096; e += 256) {
        int r = e >> 6, d = e & 63;
        int mg = m0 + r;
        int n = mg >> 8, l = mg & 255;
        long idx = (((long)(n * H + h)) * L_SEQ + l) * HD + d;
        qs[r][d] = __half2float(g_qh[idx]) + __half2float(g_ql[idx]);
    }
    __syncthreads();

    const int rr = tid >> 2, cg = tid & 3;
    float acc[16];
#pragma unroll
    for (int c = 0; c < 16; c++) acc[c] = 0.f;
#pragma unroll
    for (int d = 0; d < 64; d++) {
        float qv = qs[rr][d];
#pragma unroll
        for (int c = 0; c < 16; c++) acc[c] += qv * w[d][cg * 16 + c];
    }
    const int mg = m0 + rr;
    const int n = mg >> 8, l = mg & 255;
    const long base = (((long)(n * H + h)) * L_SEQ + l) * HD;
#pragma unroll
    for (int c = 0; c < 16; c++) g_qp[base + cg * 16 + c] = acc[c];
    if (cg == 0) {
        float sb = 0.f;
#pragma unroll
        for (int d = 0; d < 64; d++) sb += qs[rr][d] * pb[d];
        g_qb[((long)n * H + h) * L_SEQ + l] = sb;
    }
}

// ---- cpm_fused: per (n,i): full score row (qk + qp@pos^T + qb), softmax,
//      write probs hi/lo.
#define CSA 72   // fp16 elements per row (64 + 8 pad)
__global__ void __launch_bounds__(256) cpm_kernel(const float* __restrict__ pos)
{
    __shared__ __align__(16) __half sAh[16 * CSA];
    __shared__ __align__(16) __half sAl[16 * CSA];
    __shared__ __align__(16) __half sB[L_SEQ * CSA];
    __shared__ float qbs[12];
    __shared__ float wred[8][12];
    __shared__ float rowv[12];

    const int b = blockIdx.x;            // n*L + i
    const int n = b >> 8, i = b & 255;
    const int tid = threadIdx.x;
    const int lane = tid & 31, wid = tid >> 5;

    for (int e = tid; e < 1024; e += 256) {
        int h = e >> 6, c = e & 63;
        float v = (h < 12) ? g_qp[(((long)(n * H + h)) * L_SEQ + i) * HD + c] : 0.f;
        __half hb, lb;
        split1(v, hb, lb);
        sAh[h * CSA + c] = hb;
        sAl[h * CSA + c] = lb;
    }
    if (tid < 12) qbs[tid] = g_qb[((long)n * H + tid) * L_SEQ + i];

    const float4* pr = (const float4*)(pos + (((long)n * L_SEQ + i) * L_SEQ) * 64);
#pragma unroll 8
    for (int u = 0; u < 16; u++) {
        int e = tid + u * 256;
        int rr = e >> 4, cc = e & 15;
        float4 v = pr[e];
        uint2 h;
        pack4(v, h);
        *(uint2*)&sB[rr * CSA + cc * 4] = h;
    }
    __syncthreads();

    const uint32_t aB = smem_u32(sAh), aL = smem_u32(sAl), bB = smem_u32(sB);
    const int n0 = wid * 32;

    float acc[4][4];
#pragma unroll
    for (int j = 0; j < 4; j++)
#pragma unroll
        for (int r = 0; r < 4; r++) acc[j][r] = 0.f;

#pragma unroll
    for (int ks = 0; ks < 4; ks++) {
        const uint32_t kcol = (uint32_t)((ks * 16 + (lane >> 4) * 8) * 2);
        uint32_t ah[4], al[4];
        {
            uint32_t off = ((uint32_t)(lane & 15) * CSA) * 2 + kcol;
            ldm4(ah, aB + off);
            ldm4(al, aL + off);
        }
        uint32_t bh[2][4];
#pragma unroll
        for (int t = 0; t < 2; t++) {
            uint32_t off = ((uint32_t)(n0 + (lane & 15) + t * 16) * CSA) * 2 + kcol;
            ldm4(bh[t], bB + off);
        }
#pragma unroll
        for (int nt = 0; nt < 4; nt++) {
            int u = nt >> 1, p = nt & 1;
            mma16816(acc[nt], ah, bh[u][p], bh[u][p + 2]);
            mma16816(acc[nt], al, bh[u][p], bh[u][p + 2]);
        }
    }

    const int rl = lane >> 2, cl = (lane & 3) * 2;
    float sc[2][8];
#pragma unroll
    for (int g = 0; g < 2; g++) {
        const int m = g * 8 + rl;
        if (m < 12) {
            const float qb = qbs[m];
            const float* srow = g_scores + ((((long)n * H + m) * L_SEQ + i) * L_SEQ);
#pragma unroll
            for (int nt = 0; nt < 4; nt++) {
                const int j = n0 + nt * 8 + cl;
                float2 qk = *(const float2*)(srow + j);
                sc[g][2 * nt]     = qk.x + acc[nt][2 * g]     + qb;
                sc[g][2 * nt + 1] = qk.y + acc[nt][2 * g + 1] + qb;
            }
        } else {
#pragma unroll
            for (int c = 0; c < 8; c++) sc[g][c] = -1e30f;
        }
    }

    float mymax[2];
#pragma unroll
    for (int g = 0; g < 2; g++) {
        float m = sc[g][0];
#pragma unroll
        for (int c = 1; c < 8; c++) m = fmaxf(m, sc[g][c]);
        m = fmaxf(m, __shfl_xor_sync(0xffffffffu, m, 1));
        m = fmaxf(m, __shfl_xor_sync(0xffffffffu, m, 2));
        mymax[g] = m;
    }
    if ((lane & 3) == 0) {
        wred[wid][rl] = mymax[0];
        if (8 + rl < 12) wred[wid][8 + rl] = mymax[1];
    }
    __syncthreads();
    if (tid < 12) {
        float m = wred[0][tid];
#pragma unroll
        for (int w = 1; w < 8; w++) m = fmaxf(m, wred[w][tid]);
        rowv[tid] = m;
    }
    __syncthreads();
    float rmax[2];
    rmax[0] = rowv[rl];
    rmax[1] = (8 + rl < 12) ? rowv[8 + rl] : 0.f;
    __syncthreads();

    float mysum[2];
#pragma unroll
    for (int g = 0; g < 2; g++) {
        float s = 0.f;
#pragma unroll
        for (int c = 0; c < 8; c++) {
            float e = __expf(sc[g][c] - rmax[g]);
            sc[g][c] = e;
            s += e;
        }
        s += __shfl_xor_sync(0xffffffffu, s, 1);
        s += __shfl_xor_sync(0xffffffffu, s, 2);
        mysum[g] = s;
    }
    if ((lane & 3) == 0) {
        wred[wid][rl] = mysum[0];
        if (8 + rl < 12) wred[wid][8 + rl] = mysum[1];
    }
    __syncthreads();
    if (tid < 12) {
        float s = 0.f;
#pragma unroll
        for (int w = 0; w < 8; w++) s += wred[w][tid];
        rowv[tid] = 1.f / s;
    }
    __syncthreads();
    float rinv[2];
    rinv[0] = rowv[rl];
    rinv[1] = (8 + rl < 12) ? rowv[8 + rl] : 0.f;

#pragma unroll
    for (int g = 0; g < 2; g++) {
        const int m = g * 8 + rl;
        if (m < 12) {
            const long rbase = (((long)n * H + m) * L_SEQ + i) * L_SEQ;
#pragma unroll
            for (int nt = 0; nt < 4; nt++) {
                const int j = n0 + nt * 8 + cl;
                float p0 = sc[g][2 * nt] * rinv[g];
                float p1 = sc[g][2 * nt + 1] * rinv[g];
                __half h0, l0, h1, l1;
                split1(p0, h0, l0);
                split1(p1, h1, l1);
                *(__half2*)(g_ph + rbase + j) = __half2(h0, h1);
                *(__half2*)(g_pl + rbase + j) = __half2(l0, l1);
            }
        }
    }
}

// ---- out = LayerNorm(a + sum partials); optional fp16 copy ---------------
__global__ void ln_multi(const float* __restrict__ a, const float* __restrict__ p,
                         int nparts, long pstride,
                         const float* __restrict__ gamma, const float* __restrict__ beta,
                         float* __restrict__ out, __half* __restrict__ out16)
{
    const int row = blockIdx.x;
    const int t = threadIdx.x;
    __shared__ float rs[8], rq[8];
    float v[3];
    float s = 0.f, s2 = 0.f;
#pragma unroll
    for (int u = 0; u < 3; u++) {
        long idx = (long)row * E + t + u * 256;
        float x = a[idx];
        for (int z = 0; z < nparts; z++) x += p[z * pstride + idx];
        v[u] = x; s += x; s2 += x * x;
    }
#pragma unroll
    for (int o = 16; o > 0; o >>= 1) {
        s  += __shfl_xor_sync(0xffffffffu, s, o);
        s2 += __shfl_xor_sync(0xffffffffu, s2, o);
    }
    if ((t & 31) == 0) { rs[t >> 5] = s; rq[t >> 5] = s2; }
    __syncthreads();
    if (t < 32) {
        float a1 = (t < 8) ? rs[t] : 0.f;
        float a2 = (t < 8) ? rq[t] : 0.f;
#pragma unroll
        for (int o = 4; o > 0; o >>= 1) {
            a1 += __shfl_xor_sync(0xffffffffu, a1, o);
            a2 += __shfl_xor_sync(0xffffffffu, a2, o);
        }
        if (t == 0) { rs[0] = a1; rq[0] = a2; }
    }
    __syncthreads();
    float mean = rs[0] * (1.f / 768.f);
    float var  = rq[0] * (1.f / 768.f) - mean * mean;
    float r = rsqrtf(var + 1e-5f);
#pragma unroll
    for (int u = 0; u < 3; u++) {
        int c = t + u * 256;
        float o = (v[u] - mean) * r * gamma[c] + beta[c];
        out[(long)row * E + c] = o;
        if (out16) out16[(long)row * E + c] = __float2half(o);
    }
}

// =================== host launcher ===================
extern "C" void kernel_launch(void* const* d_in, const int* in_sizes, int n_in,
                              void* d_out, int out_size)
{
    const float* src    = (const float*)d_in[0];
    const float* pos    = (const float*)d_in[1];
    const float* q_w    = (const float*)d_in[2];
    const float* q_b    = (const float*)d_in[3];
    const float* k_w    = (const float*)d_in[4];
    const float* k_b    = (const float*)d_in[5];
    const float* v_w    = (const float*)d_in[6];
    const float* v_b    = (const float*)d_in[7];
    const float* p_w    = (const float*)d_in[8];
    const float* p_b    = (const float*)d_in[9];
    const float* out_w  = (const float*)d_in[10];
    const float* out_b  = (const float*)d_in[11];
    const float* lin1_w = (const float*)d_in[12];
    const float* lin1_b = (const float*)d_in[13];
    const float* lin2_w = (const float*)d_in[14];
    const float* lin2_b = (const float*)d_in[15];
    const float* n1_g   = (const float*)d_in[16];
    const float* n1_b   = (const float*)d_in[17];
    const float* n2_g   = (const float*)d_in[18];
    const float* n2_b   = (const float*)d_in[19];
    float* out = (float*)d_out;

    auto hg0 = hgemm<0>; auto hg1 = hgemm<1>; auto hg2 = hgemm<2>;
    auto pg_scores = pgemm<128, 128, 4, 0>;
    auto pg_ctx    = pgemm<256, 64, 8, 1>;
    const int smem_scores = 3 * (2 * 128 * SA * 2 + 128 * SA * 2);          // 92160
    const int smem_ctx    = 3 * (2 * 256 * SA * 2 + 64 * SA * 2);           // 138240
    cudaFuncSetAttribute(hg0, cudaFuncAttributeMaxDynamicSharedMemorySize, HSM);
    cudaFuncSetAttribute(hg1, cudaFuncAttributeMaxDynamicSharedMemorySize, HSM);
    cudaFuncSetAttribute(hg2, cudaFuncAttributeMaxDynamicSharedMemorySize, HSM);
    cudaFuncSetAttribute(pg_scores, cudaFuncAttributeMaxDynamicSharedMemorySize, smem_scores);
    cudaFuncSetAttribute(pg_ctx, cudaFuncAttributeMaxDynamicSharedMemorySize, smem_ctx);

    float *pscores, *pattn, *px1, *pff2;
    cudaGetSymbolAddress((void**)&pscores, g_scores);
    cudaGetSymbolAddress((void**)&pattn,   g_attnout);
    cudaGetSymbolAddress((void**)&px1,     g_x1);
    cudaGetSymbolAddress((void**)&pff2,    g_ff2);

    __half *qh, *ql, *kh, *vTh, *ph, *pl;
    __half *wqkv, *wout, *w1, *w2, *srch, *x1h, *ff1h, *ctxh;
    cudaGetSymbolAddress((void**)&qh,   g_qh);  cudaGetSymbolAddress((void**)&ql, g_ql);
    cudaGetSymbolAddress((void**)&kh,   g_kh);
    cudaGetSymbolAddress((void**)&vTh,  g_vTh);
    cudaGetSymbolAddress((void**)&ph,   g_ph);  cudaGetSymbolAddress((void**)&pl, g_pl);
    cudaGetSymbolAddress((void**)&wqkv, g_wqkv);
    cudaGetSymbolAddress((void**)&wout, g_wout);
    cudaGetSymbolAddress((void**)&w1,   g_w1);
    cudaGetSymbolAddress((void**)&w2,   g_w2);
    cudaGetSymbolAddress((void**)&srch, g_srch);
    cudaGetSymbolAddress((void**)&x1h,  g_x1h);
    cudaGetSymbolAddress((void**)&ff1h, g_ff1h);
    cudaGetSymbolAddress((void**)&ctxh, g_ctxh);

    // ---- single-launch fp32 -> fp16 converts (7 segments) ----
    {
        CvtArgs a;
        const float* srcs[7]  = { q_w, k_w, v_w, out_w, lin1_w, lin2_w, src };
        __half* dsts[7] = { wqkv, wqkv + E * E, wqkv + 2 * E * E, wout, w1, w2, srch };
        int sizes[7] = { E*E, E*E, E*E, E*E, FF*E, E*FF, NTOK*E };
        int acc = 0;
        for (int k = 0; k < 7; k++) {
            a.src[k] = (const float4*)srcs[k];
            a.dst[k] = (uint2*)dsts[k];
            a.start[k] = acc;
            acc += sizes[k] / 4;
        }
        a.start[7] = acc;
        cvt_all<<<(acc + 255) / 256, 256>>>(a);
    }

    // ---- fused QKV projection ----
    hg2<<<dim3(3 * E / 128, NTOK / 128, 1), 256, HSM>>>(
        srch, wqkv, q_b, k_b, v_b, nullptr, nullptr, NTOK, 3 * E, E, E);

    // ---- attention ----
    qp2_kernel<<<dim3(16, 12), 256>>>(p_w, p_b);
    pg_scores<<<dim3(2, 2, NHB), 256, smem_scores>>>(
        qh, ql, kh, pscores, nullptr, HD, (long)L_SEQ * HD, (long)L_SEQ * HD);
    cpm_kernel<<<NB * L_SEQ, 256>>>(pos);     // fused pos-scores + softmax
    pg_ctx<<<dim3(1, 1, NHB), 256, smem_ctx>>>(
        ph, pl, vTh, nullptr, ctxh, L_SEQ, (long)L_SEQ * L_SEQ, (long)HD * L_SEQ);

    // ---- output projection (split-K=2) ----
    hg0<<<dim3(E / 128, NTOK / 128, 2), 256, HSM>>>(
        ctxh, wout, out_b, nullptr, nullptr, pattn, nullptr, NTOK, E, E, E / 2);

    // ---- x1 = LN(src + partials) ----
    ln_multi<<<NTOK, 256>>>(src, pattn, 2, (long)NTOK * E, n1_g, n1_b, px1, x1h);

    // ---- FFN ----
    hg1<<<dim3(FF / 128, NTOK / 128, 1), 256, HSM>>>(
        x1h, w1, lin1_b, nullptr, nullptr, nullptr, ff1h, NTOK, FF, E, E);
    hg0<<<dim3(E / 128, NTOK / 128, 4), 256, HSM>>>(
        ff1h, w2, lin2_b, nullptr, nullptr, pff2, nullptr, NTOK, E, FF, FF / 4);

    // ---- out = LN(x1 + 4 partials) ----
    ln_multi<<<NTOK, 256>>>(px1, pff2, 4, (long)NTOK * E, n2_g, n2_b, out, nullptr);
}

// round 17
// speedup vs baseline: 1.0793x; 1.0179x over previous
#include <cuda_runtime.h>
#include <cuda_fp16.h>
#include <math.h>
#include <stdint.h>

#define L_SEQ 256
#define NB    4
#define H     12
#define HD    64
#define E     768
#define FF    3072
#define NTOK  (L_SEQ * NB)   // 1024
#define NHB   (NB * H)       // 48

// ---------------- fp32 scratch ----------------
__device__ float g_qp[NB*H*L_SEQ*HD];
__device__ float g_qb[NB*H*L_SEQ];
__device__ float g_scores[NB*H*L_SEQ*L_SEQ];
__device__ float g_attnout[2*NTOK*E];      // 2 split-K partials
__device__ float g_x1[NTOK*E];
__device__ float g_ff2[4*NTOK*E];          // 4 split-K partials

// ---------------- fp16 operands ----------------
__device__ __align__(16) __half g_qh[NB*H*L_SEQ*HD], g_ql[NB*H*L_SEQ*HD];   // (n,h,l,d)*0.125 hi/lo (lo only for qp path)
__device__ __align__(16) __half g_kh[NB*H*L_SEQ*HD];                        // (n,h,l,d) single
__device__ __align__(16) __half g_vTh[NB*H*HD*L_SEQ];                       // (n,h,d,l) single
__device__ __align__(16) __half g_ph[NB*H*L_SEQ*L_SEQ];                     // probs single
// pre-converted fp16 weights/activations
__device__ __align__(16) __half g_wqkv[3*E*E];   // [3E, E] rows: q,k,v
__device__ __align__(16) __half g_wout[E*E];
__device__ __align__(16) __half g_w1[FF*E];
__device__ __align__(16) __half g_w2[E*FF];
__device__ __align__(16) __half g_srch[NTOK*E];
__device__ __align__(16) __half g_x1h[NTOK*E];
__device__ __align__(16) __half g_ff1h[NTOK*FF];
__device__ __align__(16) __half g_ctxh[NTOK*E];

// =================== PTX helpers (sm_80-compatible only) ===================
__device__ __forceinline__ uint32_t smem_u32(const void* p) {
    uint32_t a;
    asm("{ .reg .u64 t; cvta.to.shared.u64 t, %1; cvt.u32.u64 %0, t; }" : "=r"(a) : "l"(p));
    return a;
}
__device__ __forceinline__ void cp16(uint32_t dst, const void* src) {
    asm volatile("cp.async.cg.shared.global [%0], [%1], 16;\n" :: "r"(dst), "l"(src));
}
__device__ __forceinline__ void ldm4(uint32_t* r, uint32_t a) {
    asm volatile("ldmatrix.sync.aligned.m8n8.x4.shared.b16 {%0,%1,%2,%3}, [%4];"
                 : "=r"(r[0]), "=r"(r[1]), "=r"(r[2]), "=r"(r[3]) : "r"(a));
}
__device__ __forceinline__ void mma16816(float* d, const uint32_t* a, uint32_t b0, uint32_t b1) {
    asm volatile(
        "mma.sync.aligned.m16n8k16.row.col.f32.f16.f16.f32 "
        "{%0,%1,%2,%3}, {%4,%5,%6,%7}, {%8,%9}, {%0,%1,%2,%3};"
        : "+f"(d[0]), "+f"(d[1]), "+f"(d[2]), "+f"(d[3])
        : "r"(a[0]), "r"(a[1]), "r"(a[2]), "r"(a[3]), "r"(b0), "r"(b1));
}
__device__ __forceinline__ void pack4(float4 x, uint2& h) {
    __half2 hh0(__float2half(x.x), __float2half(x.y));
    __half2 hh1(__float2half(x.z), __float2half(x.w));
    h.x = *(uint32_t*)&hh0; h.y = *(uint32_t*)&hh1;
}
__device__ __forceinline__ void split1(float v, __half& h, __half& l) {
    h = __float2half(v);
    l = __float2half(v - __half2float(h));
}

// =================== single-launch fp32 -> fp16 convert (7 segments) ======
struct CvtArgs {
    const float4* src[7];
    uint2* dst[7];
    int start[8];   // prefix sums in float4 units; start[7] = total
};
__global__ void cvt_all(CvtArgs a)
{
    int i = blockIdx.x * blockDim.x + threadIdx.x;
    if (i >= a.start[7]) return;
    int seg = 0;
#pragma unroll
    for (int k = 1; k < 7; k++) seg += (i >= a.start[k]);
    int j = i - a.start[seg];
    uint2 h;
    pack4(a.src[seg][j], h);
    a.dst[seg][j] = h;
}

// ============ fp16-operand GEMM (cp.async 3-stage, 1 sync/iter) ===========
#define SA 40
#define HTILE (128 * SA * 2)            // 10240
#define HSTG  (2 * HTILE)               // 20480
#define HSM   (3 * HSTG)                // 61440

template<int MODE>
__global__ void __launch_bounds__(256, 2) hgemm(
    const __half* __restrict__ A, const __half* __restrict__ B,
    const float* __restrict__ b0, const float* __restrict__ b1, const float* __restrict__ b2,
    float* __restrict__ C, __half* __restrict__ C16,
    int M, int N, int K, int klen)
{
    extern __shared__ char smem[];
    const uint32_t sb = smem_u32(smem);
    const int tid = threadIdx.x;
    const int lane = tid & 31, wid = tid >> 5;
    const int wm = wid & 3, wn = wid >> 2;
    const int row0 = blockIdx.y * 128, col0 = blockIdx.x * 128;
    const int kz = blockIdx.z;
    const int koff = kz * klen;

    float acc[2][8][4];
#pragma unroll
    for (int i = 0; i < 2; i++)
#pragma unroll
        for (int j = 0; j < 8; j++)
#pragma unroll
            for (int r = 0; r < 4; r++) acc[i][j][r] = 0.f;

    const int niter = klen >> 5;

    auto load = [&](int it, int s) {
        const int kk = koff + it * 32;
#pragma unroll
        for (int u = 0; u < 2; u++) {
            int e = tid + u * 256;               // 0..511
            int rr = e >> 2, cc = e & 3;
            uint32_t off = (uint32_t)((rr * SA + cc * 8) * 2);
            cp16(sb + (uint32_t)(s * HSTG) + off, A + (long)(row0 + rr) * K + kk + cc * 8);
            cp16(sb + (uint32_t)(s * HSTG) + HTILE + off, B + (long)(col0 + rr) * K + kk + cc * 8);
        }
        asm volatile("cp.async.commit_group;" ::: "memory");
    };
    auto compute = [&](int s) {
        const uint32_t base = sb + (uint32_t)(s * HSTG);
#pragma unroll
        for (int ks = 0; ks < 2; ks++) {
            const uint32_t kcol = (uint32_t)((ks * 16 + (lane >> 4) * 8) * 2);
            uint32_t ah[2][4];
            const uint32_t arow = (uint32_t)(wm * 32 + (lane & 15));
#pragma unroll
            for (int t = 0; t < 2; t++) {
                uint32_t off = ((arow + t * 16) * SA) * 2 + kcol;
                ldm4(ah[t], base + off);
            }
            uint32_t bh[4][4];
            const uint32_t brow = (uint32_t)(wn * 64 + (lane & 15));
#pragma unroll
            for (int u = 0; u < 4; u++) {
                uint32_t off = ((brow + u * 16) * SA) * 2 + kcol;
                ldm4(bh[u], base + HTILE + off);
            }
#pragma unroll
            for (int mt = 0; mt < 2; mt++)
#pragma unroll
                for (int nt = 0; nt < 8; nt++) {
                    int u = nt >> 1, p = nt & 1;
                    mma16816(acc[mt][nt], ah[mt], bh[u][p], bh[u][p + 2]);
                }
        }
    };

    load(0, 0);
    int s = 0, snext = 1;
    for (int it = 0; it < niter; it++) {
        if (it + 1 < niter) {
            load(it + 1, snext);
            asm volatile("cp.async.wait_group 1;" ::: "memory");
        } else {
            asm volatile("cp.async.wait_group 0;" ::: "memory");
        }
        __syncthreads();
        compute(s);
        s = snext;
        snext = (snext == 2) ? 0 : snext + 1;
    }

    const int rl = lane >> 2, cl = (lane & 3) * 2;
#pragma unroll
    for (int mt = 0; mt < 2; mt++) {
#pragma unroll
        for (int g = 0; g < 2; g++) {
            const int m = row0 + wm * 32 + mt * 16 + g * 8 + rl;
#pragma unroll
            for (int nt = 0; nt < 8; nt++) {
                const int n = col0 + wn * 64 + nt * 8 + cl;
                float v0 = acc[mt][nt][2 * g];
                float v1 = acc[mt][nt][2 * g + 1];
                if (MODE == 0) {
                    if (b0 && kz == 0) { v0 += b0[n]; v1 += b0[n + 1]; }
                    *(float2*)(C + (long)kz * M * N + (long)m * N + n) = make_float2(v0, v1);
                } else if (MODE == 1) {
                    v0 += b0[n]; v1 += b0[n + 1];
                    v0 = 0.5f * v0 * (1.0f + erff(v0 * 0.70710678118654752f));
                    v1 = 0.5f * v1 * (1.0f + erff(v1 * 0.70710678118654752f));
                    *(__half2*)(C16 + (long)m * N + n) =
                        __half2(__float2half(v0), __float2half(v1));
                } else { // MODE 2: QKV scatter -> fp16 operand layouts
                    const int l = m >> 2, nbb = m & 3;
#pragma unroll
                    for (int q = 0; q < 2; q++) {
                        int gcol = n + q;
                        float v = q ? v1 : v0;
                        int seg = gcol / E;
                        int cc = gcol - seg * E;
                        int hh = cc >> 6, dd = cc & 63;
                        if (seg == 0) {
                            __half hb, lb;
                            split1((v + b0[cc]) * 0.125f, hb, lb);
                            long idx = (((long)(nbb * H + hh)) * L_SEQ + l) * HD + dd;
                            g_qh[idx] = hb; g_ql[idx] = lb;
                        } else if (seg == 1) {
                            long idx = (((long)(nbb * H + hh)) * L_SEQ + l) * HD + dd;
                            g_kh[idx] = __float2half(v + b1[cc]);
                        } else {
                            long idx = (((long)(nbb * H + hh)) * HD + dd) * L_SEQ + l;
                            g_vTh[idx] = __float2half(v + b2[cc]);
                        }
                    }
                }
            }
        }
    }
}

// ======= single-fp16 batched GEMM (attention), 3-stage, 2 CTAs/SM ========
// MODE 0: scores fp32 -> C ; MODE 1: ctx -> fp16 C16 (scattered (l,n,e))
template<int TM, int TN, int NWM, int MODE>
__global__ void __launch_bounds__(256, 2) pgemm(
    const __half* __restrict__ Ah, const __half* __restrict__ Bh,
    float* __restrict__ C, __half* __restrict__ C16, int K, long sA, long sB)
{
    constexpr int TILE_A = TM * SA * 2;
    constexpr int TILE_B = TN * SA * 2;
    constexpr int STG = TILE_A + TILE_B;
    constexpr int O_AH = 0, O_BH = TILE_A;

    extern __shared__ char smem[];
    const uint32_t sb = smem_u32(smem);
    const int tid = threadIdx.x;
    const int lane = tid & 31, wid = tid >> 5;
    const int wm = wid % NWM, wn = wid / NWM;
    const int row0 = blockIdx.y * TM, col0 = blockIdx.x * TN;
    const int bz = blockIdx.z;

    const __half* pAh = Ah + (long)bz * sA;
    const __half* pBh = Bh + (long)bz * sB;

    float acc[2][8][4];
#pragma unroll
    for (int i = 0; i < 2; i++)
#pragma unroll
        for (int j = 0; j < 8; j++)
#pragma unroll
            for (int r = 0; r < 4; r++) acc[i][j][r] = 0.f;

    const int niter = K >> 5;

    auto load = [&](int it, int s) {
        const int koff = it * 32;
        for (int e = tid; e < TM * 4; e += 256) {
            int rr = e >> 2, cc = e & 3;
            uint32_t off = (uint32_t)((rr * SA + cc * 8) * 2);
            long go = (long)(row0 + rr) * K + koff + cc * 8;
            cp16(sb + (uint32_t)(s * STG) + O_AH + off, pAh + go);
        }
        for (int e = tid; e < TN * 4; e += 256) {
            int rr = e >> 2, cc = e & 3;
            uint32_t off = (uint32_t)((rr * SA + cc * 8) * 2);
            long go = (long)(col0 + rr) * K + koff + cc * 8;
            cp16(sb + (uint32_t)(s * STG) + O_BH + off, pBh + go);
        }
        asm volatile("cp.async.commit_group;" ::: "memory");
    };
    auto compute = [&](int s) {
        const uint32_t base = sb + (uint32_t)(s * STG);
#pragma unroll
        for (int ks = 0; ks < 2; ks++) {
            const uint32_t kcol = (uint32_t)((ks * 16 + (lane >> 4) * 8) * 2);
            uint32_t ah[2][4];
            const uint32_t arow = (uint32_t)(wm * 32 + (lane & 15));
#pragma unroll
            for (int t = 0; t < 2; t++) {
                uint32_t off = ((arow + t * 16) * SA) * 2 + kcol;
                ldm4(ah[t], base + O_AH + off);
            }
            uint32_t bh[4][4];
            const uint32_t brow = (uint32_t)(wn * 64 + (lane & 15));
#pragma unroll
            for (int u = 0; u < 4; u++) {
                uint32_t off = ((brow + u * 16) * SA) * 2 + kcol;
                ldm4(bh[u], base + O_BH + off);
            }
#pragma unroll
            for (int mt = 0; mt < 2; mt++)
#pragma unroll
                for (int nt = 0; nt < 8; nt++) {
                    int u = nt >> 1, p = nt & 1;
                    mma16816(acc[mt][nt], ah[mt], bh[u][p], bh[u][p + 2]);
                }
        }
    };

    load(0, 0);
    int s = 0, snext = 1;
    for (int it = 0; it < niter; it++) {
        if (it + 1 < niter) {
            load(it + 1, snext);
            asm volatile("cp.async.wait_group 1;" ::: "memory");
        } else {
            asm volatile("cp.async.wait_group 0;" ::: "memory");
        }
        __syncthreads();
        compute(s);
        s = snext;
        snext = (snext == 2) ? 0 : snext + 1;
    }

    const int rl = lane >> 2, cl = (lane & 3) * 2;
#pragma unroll
    for (int mt = 0; mt < 2; mt++) {
#pragma unroll
        for (int g = 0; g < 2; g++) {
            const int m = row0 + wm * 32 + mt * 16 + g * 8 + rl;
#pragma unroll
            for (int nt = 0; nt < 8; nt++) {
                const int n = col0 + wn * 64 + nt * 8 + cl;
                float v0 = acc[mt][nt][2 * g];
                float v1 = acc[mt][nt][2 * g + 1];
                if (MODE == 0) {
                    *(float2*)(C + (long)bz * L_SEQ * L_SEQ + (long)m * L_SEQ + n) =
                        make_float2(v0, v1);
                } else {
                    const int nb = bz / H, hh = bz % H;
                    *(__half2*)(C16 + ((long)m * NB + nb) * E + hh * HD + n) =
                        __half2(__float2half(v0), __float2half(v1));
                }
            }
        }
    }
}

// ---- qp[n,h,i,c] = sum_d q[n,h,i,d]*p_w[h*64+d,c]; qb = q . p_b ---------
// q reconstructed hi+lo: pos-score path keeps full precision.
__global__ void qp2_kernel(const float* __restrict__ p_w, const float* __restrict__ p_b)
{
    const int h = blockIdx.y;
    const int m0 = blockIdx.x * 64;
    __shared__ float w[64][65];
    __shared__ float qs[64][65];
    __shared__ float pb[64];
    const int tid = threadIdx.x;          // 256
    for (int e = tid; e < 4096; e += 256) {
        int d = e >> 6, c = e & 63;
        w[d][c] = p_w[(h * 64 + d) * 64 + c];
    }
    if (tid < 64) pb[tid] = p_b[h * 64 + tid];
    for (int e = tid; e < 4096; e += 256) {
        int r = e >> 6, d = e & 63;
        int mg = m0 + r;
        int n = mg >> 8, l = mg & 255;
        long idx = (((long)(n * H + h)) * L_SEQ + l) * HD + d;
        qs[r][d] = __half2float(g_qh[idx]) + __half2float(g_ql[idx]);
    }
    __syncthreads();

    const int rr = tid >> 2, cg = tid & 3;
    float acc[16];
#pragma unroll
    for (int c = 0; c < 16; c++) acc[c] = 0.f;
#pragma unroll
    for (int d = 0; d < 64; d++) {
        float qv = qs[rr][d];
#pragma unroll
        for (int c = 0; c < 16; c++) acc[c] += qv * w[d][cg * 16 + c];
    }
    const int mg = m0 + rr;
    const int n = mg >> 8, l = mg & 255;
    const long base = (((long)(n * H + h)) * L_SEQ + l) * HD;
#pragma unroll
    for (int c = 0; c < 16; c++) g_qp[base + cg * 16 + c] = acc[c];
    if (cg == 0) {
        float sb = 0.f;
#pragma unroll
        for (int d = 0; d < 64; d++) sb += qs[rr][d] * pb[d];
        g_qb[((long)n * H + h) * L_SEQ + l] = sb;
    }
}

// ---- cpm_fused: per (n,i): full score row (qk + qp@pos^T + qb), softmax,
//      write probs (single fp16).
#define CSA 72   // fp16 elements per row (64 + 8 pad)
__global__ void __launch_bounds__(256) cpm_kernel(const float* __restrict__ pos)
{
    __shared__ __align__(16) __half sAh[16 * CSA];
    __shared__ __align__(16) __half sAl[16 * CSA];
    __shared__ __align__(16) __half sB[L_SEQ * CSA];
    __shared__ float qbs[12];
    __shared__ float wred[8][12];
    __shared__ float rowv[12];

    const int b = blockIdx.x;            // n*L + i
    const int n = b >> 8, i = b & 255;
    const int tid = threadIdx.x;
    const int lane = tid & 31, wid = tid >> 5;

    for (int e = tid; e < 1024; e += 256) {
        int h = e >> 6, c = e & 63;
        float v = (h < 12) ? g_qp[(((long)(n * H + h)) * L_SEQ + i) * HD + c] : 0.f;
        __half hb, lb;
        split1(v, hb, lb);
        sAh[h * CSA + c] = hb;
        sAl[h * CSA + c] = lb;
    }
    if (tid < 12) qbs[tid] = g_qb[((long)n * H + tid) * L_SEQ + i];

    const float4* pr = (const float4*)(pos + (((long)n * L_SEQ + i) * L_SEQ) * 64);
#pragma unroll 8
    for (int u = 0; u < 16; u++) {
        int e = tid + u * 256;
        int rr = e >> 4, cc = e & 15;
        float4 v = pr[e];
        uint2 h;
        pack4(v, h);
        *(uint2*)&sB[rr * CSA + cc * 4] = h;
    }
    __syncthreads();

    const uint32_t aB = smem_u32(sAh), aL = smem_u32(sAl), bB = smem_u32(sB);
    const int n0 = wid * 32;

    float acc[4][4];
#pragma unroll
    for (int j = 0; j < 4; j++)
#pragma unroll
        for (int r = 0; r < 4; r++) acc[j][r] = 0.f;

#pragma unroll
    for (int ks = 0; ks < 4; ks++) {
        const uint32_t kcol = (uint32_t)((ks * 16 + (lane >> 4) * 8) * 2);
        uint32_t ah[4], al[4];
        {
            uint32_t off = ((uint32_t)(lane & 15) * CSA) * 2 + kcol;
            ldm4(ah, aB + off);
            ldm4(al, aL + off);
        }
        uint32_t bh[2][4];
#pragma unroll
        for (int t = 0; t < 2; t++) {
            uint32_t off = ((uint32_t)(n0 + (lane & 15) + t * 16) * CSA) * 2 + kcol;
            ldm4(bh[t], bB + off);
        }
#pragma unroll
        for (int nt = 0; nt < 4; nt++) {
            int u = nt >> 1, p = nt & 1;
            mma16816(acc[nt], ah, bh[u][p], bh[u][p + 2]);
            mma16816(acc[nt], al, bh[u][p], bh[u][p + 2]);
        }
    }

    const int rl = lane >> 2, cl = (lane & 3) * 2;
    float sc[2][8];
#pragma unroll
    for (int g = 0; g < 2; g++) {
        const int m = g * 8 + rl;
        if (m < 12) {
            const float qb = qbs[m];
            const float* srow = g_scores + ((((long)n * H + m) * L_SEQ + i) * L_SEQ);
#pragma unroll
            for (int nt = 0; nt < 4; nt++) {
                const int j = n0 + nt * 8 + cl;
                float2 qk = *(const float2*)(srow + j);
                sc[g][2 * nt]     = qk.x + acc[nt][2 * g]     + qb;
                sc[g][2 * nt + 1] = qk.y + acc[nt][2 * g + 1] + qb;
            }
        } else {
#pragma unroll
            for (int c = 0; c < 8; c++) sc[g][c] = -1e30f;
        }
    }

    float mymax[2];
#pragma unroll
    for (int g = 0; g < 2; g++) {
        float m = sc[g][0];
#pragma unroll
        for (int c = 1; c < 8; c++) m = fmaxf(m, sc[g][c]);
        m = fmaxf(m, __shfl_xor_sync(0xffffffffu, m, 1));
        m = fmaxf(m, __shfl_xor_sync(0xffffffffu, m, 2));
        mymax[g] = m;
    }
    if ((lane & 3) == 0) {
        wred[wid][rl] = mymax[0];
        if (8 + rl < 12) wred[wid][8 + rl] = mymax[1];
    }
    __syncthreads();
    if (tid < 12) {
        float m = wred[0][tid];
#pragma unroll
        for (int w = 1; w < 8; w++) m = fmaxf(m, wred[w][tid]);
        rowv[tid] = m;
    }
    __syncthreads();
    float rmax[2];
    rmax[0] = rowv[rl];
    rmax[1] = (8 + rl < 12) ? rowv[8 + rl] : 0.f;
    __syncthreads();

    float mysum[2];
#pragma unroll
    for (int g = 0; g < 2; g++) {
        float s = 0.f;
#pragma unroll
        for (int c = 0; c < 8; c++) {
            float e = __expf(sc[g][c] - rmax[g]);
            sc[g][c] = e;
            s += e;
        }
        s += __shfl_xor_sync(0xffffffffu, s, 1);
        s += __shfl_xor_sync(0xffffffffu, s, 2);
        mysum[g] = s;
    }
    if ((lane & 3) == 0) {
        wred[wid][rl] = mysum[0];
        if (8 + rl < 12) wred[wid][8 + rl] = mysum[1];
    }
    __syncthreads();
    if (tid < 12) {
        float s = 0.f;
#pragma unroll
        for (int w = 0; w < 8; w++) s += wred[w][tid];
        rowv[tid] = 1.f / s;
    }
    __syncthreads();
    float rinv[2];
    rinv[0] = rowv[rl];
    rinv[1] = (8 + rl < 12) ? rowv[8 + rl] : 0.f;

#pragma unroll
    for (int g = 0; g < 2; g++) {
        const int m = g * 8 + rl;
        if (m < 12) {
            const long rbase = (((long)n * H + m) * L_SEQ + i) * L_SEQ;
#pragma unroll
            for (int nt = 0; nt < 4; nt++) {
                const int j = n0 + nt * 8 + cl;
                float p0 = sc[g][2 * nt] * rinv[g];
                float p1 = sc[g][2 * nt + 1] * rinv[g];
                *(__half2*)(g_ph + rbase + j) =
                    __half2(__float2half(p0), __float2half(p1));
            }
        }
    }
}

// ---- out = LayerNorm(a + sum partials); optional fp16 copy ---------------
__global__ void ln_multi(const float* __restrict__ a, const float* __restrict__ p,
                         int nparts, long pstride,
                         const float* __restrict__ gamma, const float* __restrict__ beta,
                         float* __restrict__ out, __half* __restrict__ out16)
{
    const int row = blockIdx.x;
    const int t = threadIdx.x;
    __shared__ float rs[8], rq[8];
    float v[3];
    float s = 0.f, s2 = 0.f;
#pragma unroll
    for (int u = 0; u < 3; u++) {
        long idx = (long)row * E + t + u * 256;
        float x = a[idx];
        for (int z = 0; z < nparts; z++) x += p[z * pstride + idx];
        v[u] = x; s += x; s2 += x * x;
    }
#pragma unroll
    for (int o = 16; o > 0; o >>= 1) {
        s  += __shfl_xor_sync(0xffffffffu, s, o);
        s2 += __shfl_xor_sync(0xffffffffu, s2, o);
    }
    if ((t & 31) == 0) { rs[t >> 5] = s; rq[t >> 5] = s2; }
    __syncthreads();
    if (t < 32) {
        float a1 = (t < 8) ? rs[t] : 0.f;
        float a2 = (t < 8) ? rq[t] : 0.f;
#pragma unroll
        for (int o = 4; o > 0; o >>= 1) {
            a1 += __shfl_xor_sync(0xffffffffu, a1, o);
            a2 += __shfl_xor_sync(0xffffffffu, a2, o);
        }
        if (t == 0) { rs[0] = a1; rq[0] = a2; }
    }
    __syncthreads();
    float mean = rs[0] * (1.f / 768.f);
    float var  = rq[0] * (1.f / 768.f) - mean * mean;
    float r = rsqrtf(var + 1e-5f);
#pragma unroll
    for (int u = 0; u < 3; u++) {
        int c = t + u * 256;
        float o = (v[u] - mean) * r * gamma[c] + beta[c];
        out[(long)row * E + c] = o;
        if (out16) out16[(long)row * E + c] = __float2half(o);
    }
}

// =================== host launcher ===================
extern "C" void kernel_launch(void* const* d_in, const int* in_sizes, int n_in,
                              void* d_out, int out_size)
{
    const float* src    = (const float*)d_in[0];
    const float* pos    = (const float*)d_in[1];
    const float* q_w    = (const float*)d_in[2];
    const float* q_b    = (const float*)d_in[3];
    const float* k_w    = (const float*)d_in[4];
    const float* k_b    = (const float*)d_in[5];
    const float* v_w    = (const float*)d_in[6];
    const float* v_b    = (const float*)d_in[7];
    const float* p_w    = (const float*)d_in[8];
    const float* p_b    = (const float*)d_in[9];
    const float* out_w  = (const float*)d_in[10];
    const float* out_b  = (const float*)d_in[11];
    const float* lin1_w = (const float*)d_in[12];
    const float* lin1_b = (const float*)d_in[13];
    const float* lin2_w = (const float*)d_in[14];
    const float* lin2_b = (const float*)d_in[15];
    const float* n1_g   = (const float*)d_in[16];
    const float* n1_b   = (const float*)d_in[17];
    const float* n2_g   = (const float*)d_in[18];
    const float* n2_b   = (const float*)d_in[19];
    float* out = (float*)d_out;

    auto hg0 = hgemm<0>; auto hg1 = hgemm<1>; auto hg2 = hgemm<2>;
    auto pg_scores = pgemm<128, 128, 4, 0>;
    auto pg_ctx    = pgemm<256, 64, 8, 1>;
    const int smem_scores = 3 * (128 * SA * 2 + 128 * SA * 2);   // 61440
    const int smem_ctx    = 3 * (256 * SA * 2 + 64 * SA * 2);    // 76800
    cudaFuncSetAttribute(hg0, cudaFuncAttributeMaxDynamicSharedMemorySize, HSM);
    cudaFuncSetAttribute(hg1, cudaFuncAttributeMaxDynamicSharedMemorySize, HSM);
    cudaFuncSetAttribute(hg2, cudaFuncAttributeMaxDynamicSharedMemorySize, HSM);
    cudaFuncSetAttribute(pg_scores, cudaFuncAttributeMaxDynamicSharedMemorySize, smem_scores);
    cudaFuncSetAttribute(pg_ctx, cudaFuncAttributeMaxDynamicSharedMemorySize, smem_ctx);

    float *pscores, *pattn, *px1, *pff2;
    cudaGetSymbolAddress((void**)&pscores, g_scores);
    cudaGetSymbolAddress((void**)&pattn,   g_attnout);
    cudaGetSymbolAddress((void**)&px1,     g_x1);
    cudaGetSymbolAddress((void**)&pff2,    g_ff2);

    __half *qh, *kh, *vTh, *ph;
    __half *wqkv, *wout, *w1, *w2, *srch, *x1h, *ff1h, *ctxh;
    cudaGetSymbolAddress((void**)&qh,   g_qh);
    cudaGetSymbolAddress((void**)&kh,   g_kh);
    cudaGetSymbolAddress((void**)&vTh,  g_vTh);
    cudaGetSymbolAddress((void**)&ph,   g_ph);
    cudaGetSymbolAddress((void**)&wqkv, g_wqkv);
    cudaGetSymbolAddress((void**)&wout, g_wout);
    cudaGetSymbolAddress((void**)&w1,   g_w1);
    cudaGetSymbolAddress((void**)&w2,   g_w2);
    cudaGetSymbolAddress((void**)&srch, g_srch);
    cudaGetSymbolAddress((void**)&x1h,  g_x1h);
    cudaGetSymbolAddress((void**)&ff1h, g_ff1h);
    cudaGetSymbolAddress((void**)&ctxh, g_ctxh);

    // ---- single-launch fp32 -> fp16 converts (7 segments) ----
    {
        CvtArgs a;
        const float* srcs[7]  = { q_w, k_w, v_w, out_w, lin1_w, lin2_w, src };
        __half* dsts[7] = { wqkv, wqkv + E * E, wqkv + 2 * E * E, wout, w1, w2, srch };
        int sizes[7] = { E*E, E*E, E*E, E*E, FF*E, E*FF, NTOK*E };
        int acc = 0;
        for (int k = 0; k < 7; k++) {
            a.src[k] = (const float4*)srcs[k];
            a.dst[k] = (uint2*)dsts[k];
            a.start[k] = acc;
            acc += sizes[k] / 4;
        }
        a.start[7] = acc;
        cvt_all<<<(acc + 255) / 256, 256>>>(a);
    }

    // ---- fused QKV projection ----
    hg2<<<dim3(3 * E / 128, NTOK / 128, 1), 256, HSM>>>(
        srch, wqkv, q_b, k_b, v_b, nullptr, nullptr, NTOK, 3 * E, E, E);

    // ---- attention ----
    qp2_kernel<<<dim3(16, 12), 256>>>(p_w, p_b);
    pg_scores<<<dim3(2, 2, NHB), 256, smem_scores>>>(
        qh, kh, pscores, nullptr, HD, (long)L_SEQ * HD, (long)L_SEQ * HD);
    cpm_kernel<<<NB * L_SEQ, 256>>>(pos);     // fused pos-scores + softmax
    pg_ctx<<<dim3(1, 1, NHB), 256, smem_ctx>>>(
        ph, vTh, nullptr, ctxh, L_SEQ, (long)L_SEQ * L_SEQ, (long)HD * L_SEQ);

    // ---- output projection (split-K=2) ----
    hg0<<<dim3(E / 128, NTOK / 128, 2), 256, HSM>>>(
        ctxh, wout, out_b, nullptr, nullptr, pattn, nullptr, NTOK, E, E, E / 2);

    // ---- x1 = LN(src + partials) ----
    ln_multi<<<NTOK, 256>>>(src, pattn, 2, (long)NTOK * E, n1_g, n1_b, px1, x1h);

    // ---- FFN ----
    hg1<<<dim3(FF / 128, NTOK / 128, 1), 256, HSM>>>(
        x1h, w1, lin1_b, nullptr, nullptr, nullptr, ff1h, NTOK, FF, E, E);
    hg0<<<dim3(E / 128, NTOK / 128, 4), 256, HSM>>>(
        ff1h, w2, lin2_b, nullptr, nullptr, pff2, nullptr, NTOK, E, FF, FF / 4);

    // ---- out = LN(x1 + 4 partials) ----
    ln_multi<<<NTOK, 256>>>(px1, pff2, 4, (long)NTOK * E, n2_g, n2_b, out, nullptr);
}